// round 8
// baseline (speedup 1.0000x reference)
#include <cuda_runtime.h>
#include <cuda_bf16.h>
#include <math.h>

// Problem constants
constexpr int Cd  = 256;
constexpr int Hd  = 8;
constexpr int Ld  = 4;
constexpr int Pd  = 4;
constexpr int LQd = 2048;
constexpr int LXd = 300;
constexpr int LEN = 5440;            // input_flatten rows
constexpr int PLD = 304;             // padded ld for P (bf16 rows)
constexpr int KAA = Hd * LXd;        // 2400

// ---------------------------------------------------------------------------
// Scratch (device globals; no allocation allowed)
// ---------------------------------------------------------------------------
__device__ __align__(16) float g_off[LQd * Cd];
__device__ __align__(16) int   g_lin[LQd * Hd * Ld * Pd];
__device__ __align__(16) float g_P[Hd * Cd * LXd];          // [h][c][x] fp32
__device__ __align__(16) float g_slog[LQd * Hd * 16];
__device__ __align__(16) float g_attn_a[LQd * KAA];         // logits fp32 [q][h*300+x]
__device__ __align__(16) float g_ssum[LQd * Hd];
__device__ __align__(16) float g_headw[(Hd + 1) * Cd];
__device__ __align__(16) float g_bv0f[Hd * Cd];
__device__ __align__(16) float g_v2f[Hd * LXd * Cd];        // fp32 raw v2
__device__ __align__(16) float g_part[4][LQd * Cd];

// bf16 hi/lo operand banks
__device__ __align__(16) __nv_bfloat16 g_qh[LQd * Cd],  g_ql[LQd * Cd];
__device__ __align__(16) __nv_bfloat16 g_fh[LEN * Cd],  g_fl[LEN * Cd];
__device__ __align__(16) __nv_bfloat16 g_Ph[Hd * Cd * PLD + 64], g_Pl[Hd * Cd * PLD + 64];
__device__ __align__(16) __nv_bfloat16 g_aah[LQd * KAA], g_aal[LQd * KAA];   // attn_a weights
__device__ __align__(16) __nv_bfloat16 g_aggh[LQd * Hd * Cd], g_aggl[LQd * Hd * Cd];
__device__ __align__(16) __nv_bfloat16 g_wv0h[Hd * Cd * Cd], g_wv0l[Hd * Cd * Cd]; // [h*256+e][c]
__device__ __align__(16) __nv_bfloat16 g_v2fh[Hd * LXd * Cd], g_v2fl[Hd * LXd * Cd]; // [h*300+x][c]

// ---------------------------------------------------------------------------
// MMA helpers
// ---------------------------------------------------------------------------
__device__ __forceinline__ unsigned smem_u32(const void* p) {
    return (unsigned)__cvta_generic_to_shared(p);
}
__device__ __forceinline__ void ldsm_x4(unsigned addr, unsigned& r0, unsigned& r1,
                                        unsigned& r2, unsigned& r3) {
    asm volatile("ldmatrix.sync.aligned.m8n8.x4.shared.b16 {%0,%1,%2,%3}, [%4];"
                 : "=r"(r0), "=r"(r1), "=r"(r2), "=r"(r3) : "r"(addr));
}
__device__ __forceinline__ void ldsm_x4_trans(unsigned addr, unsigned& r0, unsigned& r1,
                                              unsigned& r2, unsigned& r3) {
    asm volatile("ldmatrix.sync.aligned.m8n8.x4.trans.shared.b16 {%0,%1,%2,%3}, [%4];"
                 : "=r"(r0), "=r"(r1), "=r"(r2), "=r"(r3) : "r"(addr));
}
__device__ __forceinline__ void mma_bf16(float* c, const unsigned* a,
                                         unsigned b0, unsigned b1) {
    asm volatile(
        "mma.sync.aligned.m16n8k16.row.col.f32.bf16.bf16.f32 "
        "{%0,%1,%2,%3},{%4,%5,%6,%7},{%8,%9},{%0,%1,%2,%3};"
        : "+f"(c[0]), "+f"(c[1]), "+f"(c[2]), "+f"(c[3])
        : "r"(a[0]), "r"(a[1]), "r"(a[2]), "r"(a[3]), "r"(b0), "r"(b1));
}
__device__ __forceinline__ void split1(float f, __nv_bfloat16* h, __nv_bfloat16* l) {
    __nv_bfloat16 hh = __float2bfloat16(f);
    *h = hh;
    *l = __float2bfloat16(f - __bfloat162float(hh));
}

// ---------------------------------------------------------------------------
// bf16x3 GEMM core: C[128 x 64 tile] = A @ B, A/B pre-split hi/lo bf16.
// A row-major [.,lda], B row-major [K][ldb]. 256 thr, 8 warps (4m x 2n),
// warp tile 32x32. kLen % 32 == 0. M multiple of 128 (no row guard).
// ---------------------------------------------------------------------------
__device__ __forceinline__ void bf3_tile(
    const __nv_bfloat16* __restrict__ Ahg, const __nv_bfloat16* __restrict__ Alg, int lda,
    const __nv_bfloat16* __restrict__ Bhg, const __nv_bfloat16* __restrict__ Blg, int ldb,
    float* __restrict__ C, int ldc, int N, int kLen)
{
    extern __shared__ __nv_bfloat16 smb[];
    __nv_bfloat16* Ah = smb;               // [128][40]
    __nv_bfloat16* Al = Ah + 128 * 40;
    __nv_bfloat16* Bh = Al + 128 * 40;     // [32][72]
    __nv_bfloat16* Bl = Bh + 32 * 72;
    const int tid = threadIdx.x, lane = tid & 31, warp = tid >> 5;
    const int wm = warp >> 1, wn = warp & 1;
    const int rowBase = blockIdx.y * 128, colBase = blockIdx.x * 64;
    float acc[2][4][4] = {};

    for (int kt = 0; kt < kLen; kt += 32) {
#pragma unroll
        for (int i = 0; i < 2; i++) {
            int idx = tid + i * 256;
            int r = idx >> 2, q = idx & 3;
            long off = (long)(rowBase + r) * lda + kt + q * 8;
            *(uint4*)&Ah[r * 40 + q * 8] = *(const uint4*)&Ahg[off];
            *(uint4*)&Al[r * 40 + q * 8] = *(const uint4*)&Alg[off];
        }
        {
            int r = tid >> 3, q = tid & 7;
            long off = (long)(kt + r) * ldb + colBase + q * 8;
            *(uint4*)&Bh[r * 72 + q * 8] = *(const uint4*)&Bhg[off];
            *(uint4*)&Bl[r * 72 + q * 8] = *(const uint4*)&Blg[off];
        }
        __syncthreads();
#pragma unroll
        for (int kk = 0; kk < 32; kk += 16) {
            unsigned ah[2][4], al[2][4];
#pragma unroll
            for (int mi = 0; mi < 2; mi++) {
                int rr = wm * 32 + mi * 16 + (lane & 15);
                int cc = kk + (lane >> 4) * 8;
                ldsm_x4(smem_u32(&Ah[rr * 40 + cc]), ah[mi][0], ah[mi][1], ah[mi][2], ah[mi][3]);
                ldsm_x4(smem_u32(&Al[rr * 40 + cc]), al[mi][0], al[mi][1], al[mi][2], al[mi][3]);
            }
#pragma unroll
            for (int nb = 0; nb < 2; nb++) {
                unsigned bh[4], bl[4];
                int rr = kk + (lane & 15);
                int cc = wn * 32 + nb * 16 + (lane >> 4) * 8;
                ldsm_x4_trans(smem_u32(&Bh[rr * 72 + cc]), bh[0], bh[1], bh[2], bh[3]);
                ldsm_x4_trans(smem_u32(&Bl[rr * 72 + cc]), bl[0], bl[1], bl[2], bl[3]);
#pragma unroll
                for (int mi = 0; mi < 2; mi++)
#pragma unroll
                    for (int t = 0; t < 2; t++) {
                        int ni = nb * 2 + t;
                        mma_bf16(acc[mi][ni], ah[mi], bh[t * 2], bh[t * 2 + 1]);
                        mma_bf16(acc[mi][ni], ah[mi], bl[t * 2], bl[t * 2 + 1]);
                        mma_bf16(acc[mi][ni], al[mi], bh[t * 2], bh[t * 2 + 1]);
                    }
            }
        }
        __syncthreads();
    }
    const int g = lane >> 2, qp = lane & 3;
#pragma unroll
    for (int mi = 0; mi < 2; mi++)
#pragma unroll
        for (int ni = 0; ni < 4; ni++)
#pragma unroll
            for (int ch = 0; ch < 2; ch++) {
                int gr = rowBase + wm * 32 + mi * 16 + g + ch * 8;
                int gc = colBase + wn * 32 + ni * 8 + qp * 2;
                if (gc < N)
                    *(float2*)&C[(long)gr * ldc + gc] =
                        make_float2(acc[mi][ni][ch * 2], acc[mi][ni][ch * 2 + 1]);
            }
}

constexpr int BF3_SMEM = (128 * 40 + 32 * 72) * 2 * 2;  // 29696 bytes

// attn_a logits: query @ P[h]
__global__ __launch_bounds__(256) void attn_gemm()
{
    int h = blockIdx.z;
    bf3_tile(g_qh, g_ql, Cd,
             g_Ph + (long)h * Cd * PLD, g_Pl + (long)h * Cd * PLD, PLD,
             g_attn_a + h * LXd, KAA, LXd, Cd);
}

// output GEMM partial slabs (split-K, 4 slabs in one launch)
__global__ __launch_bounds__(256) void out_gemm()
{
    int z = blockIdx.z;
    const __nv_bfloat16 *Ahg, *Alg, *Bhg, *Blg;
    int lda, kOff, kLen;
    if (z < 2) {
        Ahg = g_aggh; Alg = g_aggl; Bhg = g_wv0h; Blg = g_wv0l;
        lda = Hd * Cd; kOff = z * 1024; kLen = 1024;
    } else {
        Ahg = g_aah;  Alg = g_aal;  Bhg = g_v2fh; Blg = g_v2fl;
        lda = KAA; kOff = (z - 2) * 1216; kLen = (z == 2) ? 1216 : 1184;
    }
    bf3_tile(Ahg + kOff, Alg + kOff, lda,
             Bhg + (long)kOff * Cd, Blg + (long)kOff * Cd, Cd,
             g_part[z], Cd, Cd, kLen);
}

// ---------------------------------------------------------------------------
// Scrambled attn_s logits via bf16x3 MMA, pre-split operands.
// ---------------------------------------------------------------------------
__global__ __launch_bounds__(256) void slog_mma(const float* __restrict__ W_attn)
{
    extern __shared__ char sm[];
    float* Ms = (float*)sm;                                  // [64][268] (overlays A/B)
    __nv_bfloat16* Ah = (__nv_bfloat16*)sm;                  // [64][40]
    __nv_bfloat16* Al = Ah + 64 * 40;
    __nv_bfloat16* Bh = Al + 64 * 40;                        // [32][264]
    __nv_bfloat16* Bl = Bh + 32 * 264;
    __shared__ int slin[256];

    const int r = blockIdx.x, l = blockIdx.y, h = blockIdx.z;
    const int tid = threadIdx.x, lane = tid & 31, warp = tid >> 5;
    const int wm = warp & 1, wn = warp >> 1;
    const int p2 = r >> 3, b = r & 7;
    slin[tid] = g_lin[((256 * b + tid) * Hd + h) * 16 + l * 4 + p2];
    __syncthreads();

    float acc[2][8][4] = {};

    for (int ck = 0; ck < 256; ck += 32) {
        {   // A: 64 rows x 32 cols hi/lo
            int j = tid >> 2, q = tid & 3;
            long off = (long)(r + 32 * j) * Cd + ck + q * 8;
            *(uint4*)&Ah[j * 40 + q * 8] = *(const uint4*)&g_qh[off];
            *(uint4*)&Al[j * 40 + q * 8] = *(const uint4*)&g_ql[off];
        }
#pragma unroll
        for (int i = 0; i < 4; i++) {    // B: 32 gathered rows x 256 cols hi/lo
            int idx = tid + i * 256;
            int kr = idx >> 5, q = idx & 31;
            long off = (long)slin[ck + kr] * Cd + q * 8;
            *(uint4*)&Bh[kr * 264 + q * 8] = *(const uint4*)&g_fh[off];
            *(uint4*)&Bl[kr * 264 + q * 8] = *(const uint4*)&g_fl[off];
        }
        __syncthreads();
#pragma unroll
        for (int kk = 0; kk < 32; kk += 16) {
            unsigned ah[2][4], al[2][4];
#pragma unroll
            for (int mi = 0; mi < 2; mi++) {
                int rr = wm * 32 + mi * 16 + (lane & 15);
                int cc = kk + (lane >> 4) * 8;
                ldsm_x4(smem_u32(&Ah[rr * 40 + cc]), ah[mi][0], ah[mi][1], ah[mi][2], ah[mi][3]);
                ldsm_x4(smem_u32(&Al[rr * 40 + cc]), al[mi][0], al[mi][1], al[mi][2], al[mi][3]);
            }
#pragma unroll
            for (int nb = 0; nb < 4; nb++) {
                unsigned bh[4], bl[4];
                int rr = kk + (lane & 15);
                int cc = wn * 64 + nb * 16 + (lane >> 4) * 8;
                ldsm_x4_trans(smem_u32(&Bh[rr * 264 + cc]), bh[0], bh[1], bh[2], bh[3]);
                ldsm_x4_trans(smem_u32(&Bl[rr * 264 + cc]), bl[0], bl[1], bl[2], bl[3]);
#pragma unroll
                for (int mi = 0; mi < 2; mi++)
#pragma unroll
                    for (int t = 0; t < 2; t++) {
                        int ni = nb * 2 + t;
                        mma_bf16(acc[mi][ni], ah[mi], bh[t * 2], bh[t * 2 + 1]);
                        mma_bf16(acc[mi][ni], ah[mi], bl[t * 2], bl[t * 2 + 1]);
                        mma_bf16(acc[mi][ni], al[mi], bh[t * 2], bh[t * 2 + 1]);
                    }
            }
        }
        __syncthreads();
    }

    // acc -> Ms (overlays A/B; safe after the loop's trailing barrier)
    const int g = lane >> 2, qp = lane & 3;
#pragma unroll
    for (int mi = 0; mi < 2; mi++)
#pragma unroll
        for (int ni = 0; ni < 8; ni++)
#pragma unroll
            for (int ch = 0; ch < 2; ch++) {
                int row = wm * 32 + mi * 16 + g + ch * 8;
                int col = wn * 64 + ni * 8 + qp * 2;
                *(float2*)&Ms[row * 268 + col] =
                    make_float2(acc[mi][ni][ch * 2], acc[mi][ni][ch * 2 + 1]);
            }
    __syncthreads();

    // stage 2: one logit per thread
    int p = tid >> 6, j = tid & 63;
    int cstar = p * 64 + j;
    const float4* w4 = (const float4*)(W_attn + ((long)(h * Ld + l) * Cd + cstar) * Cd);
    const float* mrow = Ms + j * 268;
    float s = 0.f;
#pragma unroll 4
    for (int e4 = 0; e4 < 64; e4++) {
        float4 w = w4[e4];
        s += w.x * mrow[e4 * 4] + w.y * mrow[e4 * 4 + 1]
           + w.z * mrow[e4 * 4 + 2] + w.w * mrow[e4 * 4 + 3];
    }
    int q = r + 32 * j;
    g_slog[(q * Hd + h) * 16 + l * 4 + p] = s;
}
constexpr int SLOG_SMEM = 64 * 268 * 4;   // 68608 (>= overlaid A/B 44032)

// ---------------------------------------------------------------------------
// fp32 tiled GEMM (TB): C = A @ B^T (small prep GEMMs)
// ---------------------------------------------------------------------------
__global__ void sgemm_tb(const float* __restrict__ A, int lda, long sA,
                         const float* __restrict__ B, int ldb, long sB,
                         float* __restrict__ Cm, int ldc, long sC,
                         int M, int N, int K)
{
    __shared__ float As[16][68];
    __shared__ float Bs[16][68];
    const int tid = threadIdx.x;
    A  += (long)blockIdx.z * sA;
    B  += (long)blockIdx.z * sB;
    Cm += (long)blockIdx.z * sC;
    const int rowBase = blockIdx.y * 64, colBase = blockIdx.x * 64;
    const int tr = (tid >> 4) * 4, tc = (tid & 15) * 4;
    float acc[4][4] = {};

    for (int kt = 0; kt < K; kt += 16) {
#pragma unroll
        for (int i = 0; i < 4; i++) {
            int idx = tid + i * 256;
            int ar = idx >> 4, ac = idx & 15;
            int gr = rowBase + ar;
            As[ac][ar] = (gr < M) ? A[(long)gr * lda + kt + ac] : 0.f;
        }
#pragma unroll
        for (int i = 0; i < 4; i++) {
            int idx = tid + i * 256;
            int bn = idx >> 4, bk = idx & 15;
            int gn = colBase + bn;
            Bs[bk][bn] = (gn < N) ? B[(long)gn * ldb + kt + bk] : 0.f;
        }
        __syncthreads();
#pragma unroll
        for (int k = 0; k < 16; k++) {
            float4 av = *(const float4*)&As[k][tr];
            float4 bv = *(const float4*)&Bs[k][tc];
            float a[4] = {av.x, av.y, av.z, av.w};
            float b[4] = {bv.x, bv.y, bv.z, bv.w};
#pragma unroll
            for (int i = 0; i < 4; i++)
#pragma unroll
                for (int j = 0; j < 4; j++) acc[i][j] += a[i] * b[j];
        }
        __syncthreads();
    }
#pragma unroll
    for (int i = 0; i < 4; i++) {
        int gr = rowBase + tr + i;
        if (gr >= M) continue;
#pragma unroll
        for (int j = 0; j < 4; j++) {
            int gc = colBase + tc + j;
            if (gc < N) Cm[(long)gr * ldc + gc] = acc[i][j];
        }
    }
}

// ---------------------------------------------------------------------------
// Conversion / prep kernels
// ---------------------------------------------------------------------------
__global__ void cvt_qf(const float* __restrict__ query, const float* __restrict__ flat)
{
    long i = (long)blockIdx.x * 256 + threadIdx.x;
    if (i < (long)LQd * Cd) {
        split1(query[i], &g_qh[i], &g_ql[i]);
    } else {
        long j = i - (long)LQd * Cd;
        split1(flat[j], &g_fh[j], &g_fl[j]);
    }
}

__global__ void cvt_P()
{
    int i = blockIdx.x * 256 + threadIdx.x;   // < 8*256*300
    int hc = i / LXd, x = i - hc * LXd;
    split1(g_P[i], &g_Ph[(long)hc * PLD + x], &g_Pl[(long)hc * PLD + x]);
}

__global__ void prep_headw(const float* __restrict__ W_mix, const float* __restrict__ b_v)
{
    int c = threadIdx.x;
    float m = -1e30f;
    for (int j = 0; j <= Hd; j++) m = fmaxf(m, W_mix[c * (Hd + 1) + j]);
    float e[Hd + 1];
    float Z = 0.f;
    for (int j = 0; j <= Hd; j++) { e[j] = expf(W_mix[c * (Hd + 1) + j] - m); Z += e[j]; }
    float invZ = 1.f / Z;
    for (int j = 0; j <= Hd; j++) g_headw[j * Cd + c] = e[j] * invZ;
    for (int h = 0; h < Hd; h++)  g_bv0f[h * Cd + c] = e[h] * invZ * b_v[(2 * h) * Cd + c];
}

// wv0ft[h][e][c] = head_w[h][c] * W_v[2h][c][e]  -> bf16 hi/lo
__global__ void prep_fold(const float* __restrict__ W_v)
{
    __shared__ float t[32][33];
    int h = blockIdx.z;
    int e0 = blockIdx.x * 32, c0 = blockIdx.y * 32;
    int x = threadIdx.x, y = threadIdx.y;
    for (int i = 0; i < 32; i += 8) {
        int cc = c0 + y + i;
        t[y + i][x] = W_v[((long)(2 * h) * Cd + cc) * Cd + e0 + x];
    }
    __syncthreads();
    for (int i = 0; i < 32; i += 8) {
        int ee = e0 + y + i;
        int cc = c0 + x;
        float v = g_headw[h * Cd + cc] * t[x][y + i];
        long o = ((long)h * Cd + ee) * Cd + cc;
        split1(v, &g_wv0h[o], &g_wv0l[o]);
    }
}

// v2f[h][x][c] = head_w[h][c]*(v2_raw + b) -> bf16 hi/lo
__global__ void fold_v2f(const float* __restrict__ b_v)
{
    int i = blockIdx.x * 256 + threadIdx.x;
    int c = i & 255;
    int h = (i >> 8) / LXd;
    float v = g_headw[h * Cd + c] * (g_v2f[i] + b_v[(2 * h + 1) * Cd + c]);
    split1(v, &g_v2fh[i], &g_v2fl[i]);
}

__global__ void loc_kernel(const float* __restrict__ ref, const float* __restrict__ b_off,
                           const int* __restrict__ iss, const int* __restrict__ lsi)
{
    int id = blockIdx.x * 256 + threadIdx.x;
    if (id >= LQd * Hd * Ld * Pd) return;
    int q = id >> 7;
    int r = id & 127;
    int hh = r >> 4;
    int l = (r >> 2) & 3;
    int p = r & 3;
    int j = ((hh * Ld + l) * Pd + p) * 2;
    float off0 = g_off[q * Cd + j]     + b_off[j];
    float off1 = g_off[q * Cd + j + 1] + b_off[j + 1];
    int W0 = iss[l * 2], W1 = iss[l * 2 + 1];
    float ref0 = ref[(q * Ld + l) * 2];
    float ref1 = ref[(q * Ld + l) * 2 + 1];
    float loc0 = ref0 + off0 / (float)W1;
    float loc1 = ref1 + off1 / (float)W0;
    loc0 = fminf(fmaxf(loc0, 0.f), 0.999f);
    loc1 = fminf(fmaxf(loc1, 0.f), 0.999f);
    int ix = (int)(loc0 * (float)W0);
    int iy = (int)(loc1 * (float)W1);
    g_lin[id] = ix + iy * W0 + lsi[l];
}

// ---------------------------------------------------------------------------
// Fused softmax + key aggregation per (q,h); emits bf16 hi/lo operands.
// ---------------------------------------------------------------------------
__global__ void fuse_kernel(const float* __restrict__ flat)
{
    __shared__ float skeys[16][Cd];
    __shared__ int   slin[16];
    __shared__ float slog[16];
    __shared__ float sws[16];
    __shared__ float red[8];
    __shared__ float sm_max, sm_sum;

    const int q = blockIdx.x, h = blockIdx.y, t = threadIdx.x;
    const int warp = t >> 5, lane = t & 31;

    if (t < 16) {
        slin[t] = g_lin[(q * Hd + h) * 16 + t];
        slog[t] = g_slog[(q * Hd + h) * 16 + t];
    }
    __syncthreads();
#pragma unroll
    for (int k = 0; k < 16; k++)
        skeys[k][t] = flat[(long)slin[k] * Cd + t];

    float la0 = g_attn_a[(long)q * KAA + h * LXd + t];
    float la1 = (t < LXd - 256) ? g_attn_a[(long)q * KAA + h * LXd + 256 + t] : -1e30f;

    float m = fmaxf(la0, la1);
    if (t < 16) m = fmaxf(m, slog[t]);
#pragma unroll
    for (int o = 16; o > 0; o >>= 1) m = fmaxf(m, __shfl_xor_sync(0xffffffffu, m, o));
    if (lane == 0) red[warp] = m;
    __syncthreads();
    if (t == 0) {
        float mm = red[0];
        for (int w = 1; w < 8; w++) mm = fmaxf(mm, red[w]);
        sm_max = mm;
    }
    __syncthreads();
    m = sm_max;

    float e0 = expf(la0 - m);
    float e1 = (t < LXd - 256) ? expf(la1 - m) : 0.f;
    float es = (t < 16) ? expf(slog[t] - m) : 0.f;
    float csum = e0 + e1 + es;
#pragma unroll
    for (int o = 16; o > 0; o >>= 1) csum += __shfl_xor_sync(0xffffffffu, csum, o);
    if (lane == 0) red[warp] = csum;
    __syncthreads();
    if (t == 0) {
        float s2 = 0.f;
        for (int w = 0; w < 8; w++) s2 += red[w];
        sm_sum = s2;
    }
    __syncthreads();
    const float invZ = 1.f / sm_sum;

    {   // attn_a weights -> bf16 hi/lo, layout [q][h*300+x]
        long o = (long)q * KAA + h * LXd + t;
        split1(e0 * invZ, &g_aah[o], &g_aal[o]);
        if (t < LXd - 256) split1(e1 * invZ, &g_aah[o + 256], &g_aal[o + 256]);
    }
    if (t < 16) sws[t] = es * invZ;
    if (warp == 0) {
        float ss = (t < 16) ? es * invZ : 0.f;
#pragma unroll
        for (int o = 16; o > 0; o >>= 1) ss += __shfl_xor_sync(0xffffffffu, ss, o);
        if (t == 0) g_ssum[q * Hd + h] = ss;
    }
    __syncthreads();

    float a = 0.f;
#pragma unroll
    for (int k = 0; k < 16; k++) a += sws[k] * skeys[k][t];
    long o = (long)(q * Hd + h) * Cd + t;
    split1(a, &g_aggh[o], &g_aggl[o]);
}

// out = q*headw_last + sum_h ssum*bv0f + 4 split-K partials
__global__ void combine_out(const float* __restrict__ query, float* __restrict__ out)
{
    int i = blockIdx.x * 256 + threadIdx.x;
    int c = i & 255, q = i >> 8;
    float v = query[i] * g_headw[Hd * Cd + c];
#pragma unroll
    for (int h = 0; h < Hd; h++) v += g_ssum[q * Hd + h] * g_bv0f[h * Cd + c];
    v += g_part[0][i] + g_part[1][i] + g_part[2][i] + g_part[3][i];
    out[i] = v;
}

// ---------------------------------------------------------------------------
extern "C" void kernel_launch(void* const* d_in, const int* in_sizes, int n_in,
                              void* d_out, int out_size)
{
    const float* query  = (const float*)d_in[0];
    const float* ref    = (const float*)d_in[1];
    const float* flat   = (const float*)d_in[2];
    const int*   iss    = (const int*)  d_in[3];
    const float* ak     = (const float*)d_in[4];
    const int*   lsi    = (const int*)  d_in[5];
    const float* W_off  = (const float*)d_in[6];
    const float* b_off  = (const float*)d_in[7];
    const float* W_attn = (const float*)d_in[8];
    const float* W_v    = (const float*)d_in[9];
    const float* b_v    = (const float*)d_in[10];
    const float* W_mix  = (const float*)d_in[11];
    float* out = (float*)d_out;

    float *p_off, *p_P, *p_v2f;
    cudaGetSymbolAddress((void**)&p_off, g_off);
    cudaGetSymbolAddress((void**)&p_P,   g_P);
    cudaGetSymbolAddress((void**)&p_v2f, g_v2f);

    // one-time setup: smem opt-in + fork/join streams & events
    static int init_done = 0;
    static cudaStream_t s1, s2, s3;
    static cudaEvent_t e0, eCvt, eLoc, eAttn, ePrep;
    if (!init_done) {
        cudaFuncSetAttribute(slog_mma,
                             cudaFuncAttributeMaxDynamicSharedMemorySize, SLOG_SMEM);
        cudaStreamCreateWithFlags(&s1, cudaStreamNonBlocking);
        cudaStreamCreateWithFlags(&s2, cudaStreamNonBlocking);
        cudaStreamCreateWithFlags(&s3, cudaStreamNonBlocking);
        cudaEventCreateWithFlags(&e0,    cudaEventDisableTiming);
        cudaEventCreateWithFlags(&eCvt,  cudaEventDisableTiming);
        cudaEventCreateWithFlags(&eLoc,  cudaEventDisableTiming);
        cudaEventCreateWithFlags(&eAttn, cudaEventDisableTiming);
        cudaEventCreateWithFlags(&ePrep, cudaEventDisableTiming);
        init_done = 1;
    }

    // ---- fork ----
    cudaEventRecord(e0, 0);
    cudaStreamWaitEvent(s1, e0, 0);
    cudaStreamWaitEvent(s2, e0, 0);
    cudaStreamWaitEvent(s3, e0, 0);

    // main: operand conversion (query + flat) — feeds slog / attn
    cvt_qf<<<(LQd * Cd + LEN * Cd) / 256, 256>>>(query, flat);
    cudaEventRecord(eCvt, 0);

    // s1: off = query @ W_off^T ; sampling indices — feeds slog (g_lin)
    sgemm_tb<<<dim3(4, 32, 1), 256, 0, s1>>>(
        query, Cd, 0L, W_off, Cd, 0L, p_off, Cd, 0L, LQd, Cd, Cd);
    loc_kernel<<<(LQd * Hd * Ld * Pd + 255) / 256, 256, 0, s1>>>(ref, b_off, iss, lsi);
    cudaEventRecord(eLoc, s1);

    // s2: P[h] = Wadd[h] @ ak^T -> split -> attn_a GEMM (needs eCvt for g_qh)
    sgemm_tb<<<dim3((LXd + 63) / 64, (Cd + 63) / 64, Hd), 256, 0, s2>>>(
        W_attn + 4L * Cd * Cd, Cd, 4L * Cd * Cd, ak, Cd, 0L,
        p_P, LXd, (long)Cd * LXd, Cd, LXd, Cd);
    cvt_P<<<Hd * Cd * LXd / 256, 256, 0, s2>>>();
    cudaStreamWaitEvent(s2, eCvt, 0);
    attn_gemm<<<dim3((LXd + 63) / 64, LQd / 128, Hd), 256, BF3_SMEM, s2>>>();
    cudaEventRecord(eAttn, s2);

    // s3: head mixing + value-side folds — feeds out_gemm / combine
    prep_headw<<<1, 256, 0, s3>>>(W_mix, b_v);
    sgemm_tb<<<dim3((Cd + 63) / 64, (LXd + 63) / 64, Hd), 256, 0, s3>>>(
        ak, Cd, 0L, W_v + (long)Cd * Cd, Cd, 2L * Cd * Cd,
        p_v2f, Cd, (long)LXd * Cd, LXd, Cd, Cd);
    fold_v2f<<<Hd * LXd, 256, 0, s3>>>(b_v);
    prep_fold<<<dim3(8, 8, Hd), dim3(32, 8), 0, s3>>>(W_v);
    cudaEventRecord(ePrep, s3);

    // main: scrambled attn_s logits (needs cvt [program order] + lin)
    cudaStreamWaitEvent(0, eLoc, 0);
    slog_mma<<<dim3(32, Ld, Hd), 256, SLOG_SMEM>>>(W_attn);

    // main: softmax + aggregation (needs slog + attn_a)
    cudaStreamWaitEvent(0, eAttn, 0);
    fuse_kernel<<<dim3(LQd, Hd), 256>>>(flat);

    // main: output GEMMs (needs fuse + folds), then combine — join complete
    cudaStreamWaitEvent(0, ePrep, 0);
    out_gemm<<<dim3(Cd / 64, LQd / 128, 4), 256, BF3_SMEM>>>();
    combine_out<<<LQd * Cd / 256, 256>>>(query, out);
}

// round 11
// speedup vs baseline: 1.3851x; 1.3851x over previous
#include <cuda_runtime.h>
#include <cuda_bf16.h>
#include <math.h>

// Problem constants
constexpr int Cd  = 256;
constexpr int Hd  = 8;
constexpr int Ld  = 4;
constexpr int Pd  = 4;
constexpr int LQd = 2048;
constexpr int LXd = 300;
constexpr int LEN = 5440;            // input_flatten rows
constexpr int PLD = 304;             // padded ld for [.,300] bf16/fp32 panels
constexpr int KAA = Hd * LXd;        // 2400

// ---------------------------------------------------------------------------
// Scratch (device globals; no allocation allowed)
// ---------------------------------------------------------------------------
__device__ __align__(16) float g_off[LQd * Cd];
__device__ __align__(16) int   g_lin[LQd * Hd * Ld * Pd];
__device__ __align__(16) float g_slog[LQd * Hd * 16];
__device__ __align__(16) float g_attn_a[LQd * KAA];         // logits fp32 [q][h*300+x]
__device__ __align__(16) float g_ssum[LQd * Hd];
__device__ __align__(16) float g_headw[(Hd + 1) * Cd];
__device__ __align__(16) float g_bv0f[Hd * Cd];
__device__ __align__(16) float g_v2t[Hd * Cd * PLD + 64];   // fp32 v2^T [h][c][x]
__device__ __align__(16) float g_part[4][LQd * Cd];

// bf16 hi/lo operand banks
__device__ __align__(16) __nv_bfloat16 g_qh[LQd * Cd],  g_ql[LQd * Cd];
__device__ __align__(16) __nv_bfloat16 g_fh[LEN * Cd],  g_fl[LEN * Cd];
__device__ __align__(16) __nv_bfloat16 g_akTh[Cd * PLD + 64], g_akTl[Cd * PLD + 64];
__device__ __align__(16) __nv_bfloat16 g_wah[Hd * Cd * Cd],  g_wal[Hd * Cd * Cd];   // Wadd
__device__ __align__(16) __nv_bfloat16 g_wv1h[Hd * Cd * Cd], g_wv1l[Hd * Cd * Cd];  // Wv1
__device__ __align__(16) __nv_bfloat16 g_Ph[Hd * Cd * PLD + 64], g_Pl[Hd * Cd * PLD + 64];
__device__ __align__(16) __nv_bfloat16 g_aah[LQd * KAA], g_aal[LQd * KAA];   // attn_a weights
__device__ __align__(16) __nv_bfloat16 g_aggh[LQd * Hd * Cd], g_aggl[LQd * Hd * Cd];
__device__ __align__(16) __nv_bfloat16 g_wv0h[Hd * Cd * Cd], g_wv0l[Hd * Cd * Cd]; // [h*256+e][c]
__device__ __align__(16) __nv_bfloat16 g_v2fh[Hd * LXd * Cd], g_v2fl[Hd * LXd * Cd]; // [h*300+x][c]

// ---------------------------------------------------------------------------
// MMA helpers
// ---------------------------------------------------------------------------
__device__ __forceinline__ unsigned smem_u32(const void* p) {
    return (unsigned)__cvta_generic_to_shared(p);
}
__device__ __forceinline__ void ldsm_x4(unsigned addr, unsigned& r0, unsigned& r1,
                                        unsigned& r2, unsigned& r3) {
    asm volatile("ldmatrix.sync.aligned.m8n8.x4.shared.b16 {%0,%1,%2,%3}, [%4];"
                 : "=r"(r0), "=r"(r1), "=r"(r2), "=r"(r3) : "r"(addr));
}
__device__ __forceinline__ void ldsm_x4_trans(unsigned addr, unsigned& r0, unsigned& r1,
                                              unsigned& r2, unsigned& r3) {
    asm volatile("ldmatrix.sync.aligned.m8n8.x4.trans.shared.b16 {%0,%1,%2,%3}, [%4];"
                 : "=r"(r0), "=r"(r1), "=r"(r2), "=r"(r3) : "r"(addr));
}
__device__ __forceinline__ void mma_bf16(float* c, const unsigned* a,
                                         unsigned b0, unsigned b1) {
    asm volatile(
        "mma.sync.aligned.m16n8k16.row.col.f32.bf16.bf16.f32 "
        "{%0,%1,%2,%3},{%4,%5,%6,%7},{%8,%9},{%0,%1,%2,%3};"
        : "+f"(c[0]), "+f"(c[1]), "+f"(c[2]), "+f"(c[3])
        : "r"(a[0]), "r"(a[1]), "r"(a[2]), "r"(a[3]), "r"(b0), "r"(b1));
}
__device__ __forceinline__ void split1(float f, __nv_bfloat16* h, __nv_bfloat16* l) {
    __nv_bfloat16 hh = __float2bfloat16(f);
    *h = hh;
    *l = __float2bfloat16(f - __bfloat162float(hh));
}

// ---------------------------------------------------------------------------
// bf16x3 GEMM core: C[128 x 64 tile] = A @ B, A/B pre-split hi/lo bf16.
// A row-major [.,lda], B row-major [K][ldb]. 256 thr, 8 warps (4m x 2n),
// warp tile 32x32. kLen % 32 == 0. M multiple of 128 (no row guard).
// SPLIT=false: fp32 store to C.  SPLIT=true: hi/lo bf16 store to Ch/Cl.
// ---------------------------------------------------------------------------
template <bool SPLIT>
__device__ __forceinline__ void bf3_tile(
    const __nv_bfloat16* __restrict__ Ahg, const __nv_bfloat16* __restrict__ Alg, int lda,
    const __nv_bfloat16* __restrict__ Bhg, const __nv_bfloat16* __restrict__ Blg, int ldb,
    float* __restrict__ C, __nv_bfloat16* __restrict__ Ch, __nv_bfloat16* __restrict__ Cl,
    int ldc, int N, int kLen)
{
    extern __shared__ __nv_bfloat16 smb[];
    __nv_bfloat16* Ah = smb;               // [128][40]
    __nv_bfloat16* Al = Ah + 128 * 40;
    __nv_bfloat16* Bh = Al + 128 * 40;     // [32][72]
    __nv_bfloat16* Bl = Bh + 32 * 72;
    const int tid = threadIdx.x, lane = tid & 31, warp = tid >> 5;
    const int wm = warp >> 1, wn = warp & 1;
    const int rowBase = blockIdx.y * 128, colBase = blockIdx.x * 64;
    float acc[2][4][4] = {};

    for (int kt = 0; kt < kLen; kt += 32) {
#pragma unroll
        for (int i = 0; i < 2; i++) {
            int idx = tid + i * 256;
            int r = idx >> 2, q = idx & 3;
            long off = (long)(rowBase + r) * lda + kt + q * 8;
            *(uint4*)&Ah[r * 40 + q * 8] = *(const uint4*)&Ahg[off];
            *(uint4*)&Al[r * 40 + q * 8] = *(const uint4*)&Alg[off];
        }
        {
            int r = tid >> 3, q = tid & 7;
            long off = (long)(kt + r) * ldb + colBase + q * 8;
            *(uint4*)&Bh[r * 72 + q * 8] = *(const uint4*)&Bhg[off];
            *(uint4*)&Bl[r * 72 + q * 8] = *(const uint4*)&Blg[off];
        }
        __syncthreads();
#pragma unroll
        for (int kk = 0; kk < 32; kk += 16) {
            unsigned ah[2][4], al[2][4];
#pragma unroll
            for (int mi = 0; mi < 2; mi++) {
                int rr = wm * 32 + mi * 16 + (lane & 15);
                int cc = kk + (lane >> 4) * 8;
                ldsm_x4(smem_u32(&Ah[rr * 40 + cc]), ah[mi][0], ah[mi][1], ah[mi][2], ah[mi][3]);
                ldsm_x4(smem_u32(&Al[rr * 40 + cc]), al[mi][0], al[mi][1], al[mi][2], al[mi][3]);
            }
#pragma unroll
            for (int nb = 0; nb < 2; nb++) {
                unsigned bh[4], bl[4];
                int rr = kk + (lane & 15);
                int cc = wn * 32 + nb * 16 + (lane >> 4) * 8;
                ldsm_x4_trans(smem_u32(&Bh[rr * 72 + cc]), bh[0], bh[1], bh[2], bh[3]);
                ldsm_x4_trans(smem_u32(&Bl[rr * 72 + cc]), bl[0], bl[1], bl[2], bl[3]);
#pragma unroll
                for (int mi = 0; mi < 2; mi++)
#pragma unroll
                    for (int t = 0; t < 2; t++) {
                        int ni = nb * 2 + t;
                        mma_bf16(acc[mi][ni], ah[mi], bh[t * 2], bh[t * 2 + 1]);
                        mma_bf16(acc[mi][ni], ah[mi], bl[t * 2], bl[t * 2 + 1]);
                        mma_bf16(acc[mi][ni], al[mi], bh[t * 2], bh[t * 2 + 1]);
                    }
            }
        }
        __syncthreads();
    }
    const int g = lane >> 2, qp = lane & 3;
#pragma unroll
    for (int mi = 0; mi < 2; mi++)
#pragma unroll
        for (int ni = 0; ni < 4; ni++)
#pragma unroll
            for (int ch = 0; ch < 2; ch++) {
                int gr = rowBase + wm * 32 + mi * 16 + g + ch * 8;
                int gc = colBase + wn * 32 + ni * 8 + qp * 2;
                if (gc < N) {
                    if (SPLIT) {
                        long o = (long)gr * ldc + gc;
                        split1(acc[mi][ni][ch * 2],     &Ch[o],     &Cl[o]);
                        if (gc + 1 < N)
                            split1(acc[mi][ni][ch * 2 + 1], &Ch[o + 1], &Cl[o + 1]);
                    } else {
                        *(float2*)&C[(long)gr * ldc + gc] =
                            make_float2(acc[mi][ni][ch * 2], acc[mi][ni][ch * 2 + 1]);
                    }
                }
            }
}

constexpr int BF3_SMEM = (128 * 40 + 32 * 72) * 2 * 2;  // 29696 bytes

// attn_a logits: query @ P[h]
__global__ __launch_bounds__(256) void attn_gemm()
{
    int h = blockIdx.z;
    bf3_tile<false>(g_qh, g_ql, Cd,
                    g_Ph + (long)h * Cd * PLD, g_Pl + (long)h * Cd * PLD, PLD,
                    g_attn_a + h * LXd, nullptr, nullptr, KAA, LXd, Cd);
}

// P[h] = Wadd[h] @ akT  -> hi/lo split store [h][c][PLD]
__global__ __launch_bounds__(256) void P_gemm()
{
    int h = blockIdx.z;
    bf3_tile<true>(g_wah + (long)h * Cd * Cd, g_wal + (long)h * Cd * Cd, Cd,
                   g_akTh, g_akTl, PLD,
                   nullptr, g_Ph + (long)h * Cd * PLD, g_Pl + (long)h * Cd * PLD,
                   PLD, LXd, Cd);
}

// v2^T[h] = Wv1[h] @ akT  -> fp32 [h][c][PLD]
__global__ __launch_bounds__(256) void v2t_gemm()
{
    int h = blockIdx.z;
    bf3_tile<false>(g_wv1h + (long)h * Cd * Cd, g_wv1l + (long)h * Cd * Cd, Cd,
                    g_akTh, g_akTl, PLD,
                    g_v2t + (long)h * Cd * PLD, nullptr, nullptr, PLD, LXd, Cd);
}

// output GEMM partial slabs (split-K, 4 slabs in one launch)
__global__ __launch_bounds__(256) void out_gemm()
{
    int z = blockIdx.z;
    const __nv_bfloat16 *Ahg, *Alg, *Bhg, *Blg;
    int lda, kOff, kLen;
    if (z < 2) {
        Ahg = g_aggh; Alg = g_aggl; Bhg = g_wv0h; Blg = g_wv0l;
        lda = Hd * Cd; kOff = z * 1024; kLen = 1024;
    } else {
        Ahg = g_aah;  Alg = g_aal;  Bhg = g_v2fh; Blg = g_v2fl;
        lda = KAA; kOff = (z - 2) * 1216; kLen = (z == 2) ? 1216 : 1184;
    }
    bf3_tile<false>(Ahg + kOff, Alg + kOff, lda,
                    Bhg + (long)kOff * Cd, Blg + (long)kOff * Cd, Cd,
                    g_part[z], nullptr, nullptr, Cd, Cd, kLen);
}

// ---------------------------------------------------------------------------
// Scrambled attn_s logits via bf16x3 MMA, pre-split operands.
// ---------------------------------------------------------------------------
__global__ __launch_bounds__(256) void slog_mma(const float* __restrict__ W_attn)
{
    extern __shared__ char sm[];
    float* Ms = (float*)sm;                                  // [64][268] (overlays A/B)
    __nv_bfloat16* Ah = (__nv_bfloat16*)sm;                  // [64][40]
    __nv_bfloat16* Al = Ah + 64 * 40;
    __nv_bfloat16* Bh = Al + 64 * 40;                        // [32][264]
    __nv_bfloat16* Bl = Bh + 32 * 264;
    __shared__ int slin[256];

    const int r = blockIdx.x, l = blockIdx.y, h = blockIdx.z;
    const int tid = threadIdx.x, lane = tid & 31, warp = tid >> 5;
    const int wm = warp & 1, wn = warp >> 1;
    const int p2 = r >> 3, b = r & 7;
    slin[tid] = g_lin[((256 * b + tid) * Hd + h) * 16 + l * 4 + p2];
    __syncthreads();

    float acc[2][8][4] = {};

    for (int ck = 0; ck < 256; ck += 32) {
        {   // A: 64 rows x 32 cols hi/lo
            int j = tid >> 2, q = tid & 3;
            long off = (long)(r + 32 * j) * Cd + ck + q * 8;
            *(uint4*)&Ah[j * 40 + q * 8] = *(const uint4*)&g_qh[off];
            *(uint4*)&Al[j * 40 + q * 8] = *(const uint4*)&g_ql[off];
        }
#pragma unroll
        for (int i = 0; i < 4; i++) {    // B: 32 gathered rows x 256 cols hi/lo
            int idx = tid + i * 256;
            int kr = idx >> 5, q = idx & 31;
            long off = (long)slin[ck + kr] * Cd + q * 8;
            *(uint4*)&Bh[kr * 264 + q * 8] = *(const uint4*)&g_fh[off];
            *(uint4*)&Bl[kr * 264 + q * 8] = *(const uint4*)&g_fl[off];
        }
        __syncthreads();
#pragma unroll
        for (int kk = 0; kk < 32; kk += 16) {
            unsigned ah[2][4], al[2][4];
#pragma unroll
            for (int mi = 0; mi < 2; mi++) {
                int rr = wm * 32 + mi * 16 + (lane & 15);
                int cc = kk + (lane >> 4) * 8;
                ldsm_x4(smem_u32(&Ah[rr * 40 + cc]), ah[mi][0], ah[mi][1], ah[mi][2], ah[mi][3]);
                ldsm_x4(smem_u32(&Al[rr * 40 + cc]), al[mi][0], al[mi][1], al[mi][2], al[mi][3]);
            }
#pragma unroll
            for (int nb = 0; nb < 4; nb++) {
                unsigned bh[4], bl[4];
                int rr = kk + (lane & 15);
                int cc = wn * 64 + nb * 16 + (lane >> 4) * 8;
                ldsm_x4_trans(smem_u32(&Bh[rr * 264 + cc]), bh[0], bh[1], bh[2], bh[3]);
                ldsm_x4_trans(smem_u32(&Bl[rr * 264 + cc]), bl[0], bl[1], bl[2], bl[3]);
#pragma unroll
                for (int mi = 0; mi < 2; mi++)
#pragma unroll
                    for (int t = 0; t < 2; t++) {
                        int ni = nb * 2 + t;
                        mma_bf16(acc[mi][ni], ah[mi], bh[t * 2], bh[t * 2 + 1]);
                        mma_bf16(acc[mi][ni], ah[mi], bl[t * 2], bl[t * 2 + 1]);
                        mma_bf16(acc[mi][ni], al[mi], bh[t * 2], bh[t * 2 + 1]);
                    }
            }
        }
        __syncthreads();
    }

    // acc -> Ms (overlays A/B; safe after the loop's trailing barrier)
    const int g = lane >> 2, qp = lane & 3;
#pragma unroll
    for (int mi = 0; mi < 2; mi++)
#pragma unroll
        for (int ni = 0; ni < 8; ni++)
#pragma unroll
            for (int ch = 0; ch < 2; ch++) {
                int row = wm * 32 + mi * 16 + g + ch * 8;
                int col = wn * 64 + ni * 8 + qp * 2;
                *(float2*)&Ms[row * 268 + col] =
                    make_float2(acc[mi][ni][ch * 2], acc[mi][ni][ch * 2 + 1]);
            }
    __syncthreads();

    // stage 2: one logit per thread
    int p = tid >> 6, j = tid & 63;
    int cstar = p * 64 + j;
    const float4* w4 = (const float4*)(W_attn + ((long)(h * Ld + l) * Cd + cstar) * Cd);
    const float* mrow = Ms + j * 268;
    float s = 0.f;
#pragma unroll 4
    for (int e4 = 0; e4 < 64; e4++) {
        float4 w = w4[e4];
        s += w.x * mrow[e4 * 4] + w.y * mrow[e4 * 4 + 1]
           + w.z * mrow[e4 * 4 + 2] + w.w * mrow[e4 * 4 + 3];
    }
    int q = r + 32 * j;
    g_slog[(q * Hd + h) * 16 + l * 4 + p] = s;
}
constexpr int SLOG_SMEM = 64 * 268 * 4;   // 68608 (>= overlaid A/B 44032)

// ---------------------------------------------------------------------------
// fp32 tiled GEMM (TB): C = A @ B^T  (off-projection only — index-sensitive)
// ---------------------------------------------------------------------------
__global__ void sgemm_tb(const float* __restrict__ A, int lda,
                         const float* __restrict__ B, int ldb,
                         float* __restrict__ Cm, int ldc,
                         int M, int N, int K)
{
    __shared__ float As[16][68];
    __shared__ float Bs[16][68];
    const int tid = threadIdx.x;
    const int rowBase = blockIdx.y * 64, colBase = blockIdx.x * 64;
    const int tr = (tid >> 4) * 4, tc = (tid & 15) * 4;
    float acc[4][4] = {};

    for (int kt = 0; kt < K; kt += 16) {
#pragma unroll
        for (int i = 0; i < 4; i++) {
            int idx = tid + i * 256;
            int ar = idx >> 4, ac = idx & 15;
            int gr = rowBase + ar;
            As[ac][ar] = (gr < M) ? A[(long)gr * lda + kt + ac] : 0.f;
        }
#pragma unroll
        for (int i = 0; i < 4; i++) {
            int idx = tid + i * 256;
            int bn = idx >> 4, bk = idx & 15;
            int gn = colBase + bn;
            Bs[bk][bn] = (gn < N) ? B[(long)gn * ldb + kt + bk] : 0.f;
        }
        __syncthreads();
#pragma unroll
        for (int k = 0; k < 16; k++) {
            float4 av = *(const float4*)&As[k][tr];
            float4 bv = *(const float4*)&Bs[k][tc];
            float a[4] = {av.x, av.y, av.z, av.w};
            float b[4] = {bv.x, bv.y, bv.z, bv.w};
#pragma unroll
            for (int i = 0; i < 4; i++)
#pragma unroll
                for (int j = 0; j < 4; j++) acc[i][j] += a[i] * b[j];
        }
        __syncthreads();
    }
#pragma unroll
    for (int i = 0; i < 4; i++) {
        int gr = rowBase + tr + i;
        if (gr >= M) continue;
#pragma unroll
        for (int j = 0; j < 4; j++) {
            int gc = colBase + tc + j;
            if (gc < N) Cm[(long)gr * ldc + gc] = acc[i][j];
        }
    }
}

// ---------------------------------------------------------------------------
// Conversion / prep kernels
// ---------------------------------------------------------------------------
__global__ void cvt_qf(const float* __restrict__ query, const float* __restrict__ flat)
{
    long i = (long)blockIdx.x * 256 + threadIdx.x;
    if (i < (long)LQd * Cd) {
        split1(query[i], &g_qh[i], &g_ql[i]);
    } else {
        long j = i - (long)LQd * Cd;
        split1(flat[j], &g_fh[j], &g_fl[j]);
    }
}

// ak [300][256] -> akT hi/lo [256][304] (zero-padded cols 300..303)
__global__ void cvt_akT(const float* __restrict__ ak)
{
    __shared__ float t[32][33];
    int k0 = blockIdx.x * 32;   // akT row base (ak col)
    int x0 = blockIdx.y * 32;   // akT col base (ak row)
    int x = threadIdx.x, y = threadIdx.y;   // block (32,8)
    for (int i = 0; i < 32; i += 8) {
        int xx = x0 + y + i;
        t[y + i][x] = (xx < LXd) ? ak[(long)xx * Cd + k0 + x] : 0.f;
    }
    __syncthreads();
    for (int i = 0; i < 32; i += 8) {
        int kk = k0 + y + i;
        int xx = x0 + x;
        if (xx < PLD) {
            long o = (long)kk * PLD + xx;
            split1(t[x][y + i], &g_akTh[o], &g_akTl[o]);
        }
    }
}

// Wadd (W_attn[4h+4]) and Wv1 (W_v[2h+1]) -> bf16 hi/lo
__global__ void cvt_wts(const float* __restrict__ W_attn, const float* __restrict__ W_v)
{
    long i = (long)blockIdx.x * 256 + threadIdx.x;
    const long half = (long)Hd * Cd * Cd;
    if (i < half) {
        int h = (int)(i >> 16);
        long rem = i & 65535;
        split1(W_attn[((long)(4 * h + 4) << 16) + rem], &g_wah[i], &g_wal[i]);
    } else {
        long j = i - half;
        int h = (int)(j >> 16);
        long rem = j & 65535;
        split1(W_v[((long)(2 * h + 1) << 16) + rem], &g_wv1h[j], &g_wv1l[j]);
    }
}

__global__ void prep_headw(const float* __restrict__ W_mix, const float* __restrict__ b_v)
{
    int c = threadIdx.x;
    float m = -1e30f;
    for (int j = 0; j <= Hd; j++) m = fmaxf(m, W_mix[c * (Hd + 1) + j]);
    float e[Hd + 1];
    float Z = 0.f;
    for (int j = 0; j <= Hd; j++) { e[j] = expf(W_mix[c * (Hd + 1) + j] - m); Z += e[j]; }
    float invZ = 1.f / Z;
    for (int j = 0; j <= Hd; j++) g_headw[j * Cd + c] = e[j] * invZ;
    for (int h = 0; h < Hd; h++)  g_bv0f[h * Cd + c] = e[h] * invZ * b_v[(2 * h) * Cd + c];
}

// wv0ft[h][e][c] = head_w[h][c] * W_v[2h][c][e]  -> bf16 hi/lo
__global__ void prep_fold(const float* __restrict__ W_v)
{
    __shared__ float t[32][33];
    int h = blockIdx.z;
    int e0 = blockIdx.x * 32, c0 = blockIdx.y * 32;
    int x = threadIdx.x, y = threadIdx.y;
    for (int i = 0; i < 32; i += 8) {
        int cc = c0 + y + i;
        t[y + i][x] = W_v[((long)(2 * h) * Cd + cc) * Cd + e0 + x];
    }
    __syncthreads();
    for (int i = 0; i < 32; i += 8) {
        int ee = e0 + y + i;
        int cc = c0 + x;
        float v = g_headw[h * Cd + cc] * t[x][y + i];
        long o = ((long)h * Cd + ee) * Cd + cc;
        split1(v, &g_wv0h[o], &g_wv0l[o]);
    }
}

// v2f[h*300+x][c] = head_w[h][c]*(v2t[h][c][x] + bv1[h][c]) -> bf16 hi/lo (transposed)
__global__ void fold_v2t(const float* __restrict__ b_v)
{
    __shared__ float t[32][33];
    int h = blockIdx.z;
    int c0 = blockIdx.x * 32, x0 = blockIdx.y * 32;
    int x = threadIdx.x, y = threadIdx.y;   // block (32,8)
    for (int i = 0; i < 32; i += 8) {
        int cc = c0 + y + i;
        t[y + i][x] = g_v2t[((long)h * Cd + cc) * PLD + x0 + x];
    }
    __syncthreads();
    for (int i = 0; i < 32; i += 8) {
        int xx = x0 + y + i;
        int cc = c0 + x;
        if (xx < LXd) {
            float v = g_headw[h * Cd + cc] * (t[x][y + i] + b_v[(2 * h + 1) * Cd + cc]);
            long o = (long)(h * LXd + xx) * Cd + cc;
            split1(v, &g_v2fh[o], &g_v2fl[o]);
        }
    }
}

__global__ void loc_kernel(const float* __restrict__ ref, const float* __restrict__ b_off,
                           const int* __restrict__ iss, const int* __restrict__ lsi)
{
    int id = blockIdx.x * 256 + threadIdx.x;
    if (id >= LQd * Hd * Ld * Pd) return;
    int q = id >> 7;
    int r = id & 127;
    int hh = r >> 4;
    int l = (r >> 2) & 3;
    int p = r & 3;
    int j = ((hh * Ld + l) * Pd + p) * 2;
    float off0 = g_off[q * Cd + j]     + b_off[j];
    float off1 = g_off[q * Cd + j + 1] + b_off[j + 1];
    int W0 = iss[l * 2], W1 = iss[l * 2 + 1];
    float ref0 = ref[(q * Ld + l) * 2];
    float ref1 = ref[(q * Ld + l) * 2 + 1];
    float loc0 = ref0 + off0 / (float)W1;
    float loc1 = ref1 + off1 / (float)W0;
    loc0 = fminf(fmaxf(loc0, 0.f), 0.999f);
    loc1 = fminf(fmaxf(loc1, 0.f), 0.999f);
    int ix = (int)(loc0 * (float)W0);
    int iy = (int)(loc1 * (float)W1);
    g_lin[id] = ix + iy * W0 + lsi[l];
}

// ---------------------------------------------------------------------------
// Fused softmax + key aggregation per (q,h); emits bf16 hi/lo operands.
// ---------------------------------------------------------------------------
__global__ void fuse_kernel(const float* __restrict__ flat)
{
    __shared__ float skeys[16][Cd];
    __shared__ int   slin[16];
    __shared__ float slog[16];
    __shared__ float sws[16];
    __shared__ float red[8];
    __shared__ float sm_max, sm_sum;

    const int q = blockIdx.x, h = blockIdx.y, t = threadIdx.x;
    const int warp = t >> 5, lane = t & 31;

    if (t < 16) {
        slin[t] = g_lin[(q * Hd + h) * 16 + t];
        slog[t] = g_slog[(q * Hd + h) * 16 + t];
    }
    __syncthreads();
#pragma unroll
    for (int k = 0; k < 16; k++)
        skeys[k][t] = flat[(long)slin[k] * Cd + t];

    float la0 = g_attn_a[(long)q * KAA + h * LXd + t];
    float la1 = (t < LXd - 256) ? g_attn_a[(long)q * KAA + h * LXd + 256 + t] : -1e30f;

    float m = fmaxf(la0, la1);
    if (t < 16) m = fmaxf(m, slog[t]);
#pragma unroll
    for (int o = 16; o > 0; o >>= 1) m = fmaxf(m, __shfl_xor_sync(0xffffffffu, m, o));
    if (lane == 0) red[warp] = m;
    __syncthreads();
    if (t == 0) {
        float mm = red[0];
        for (int w = 1; w < 8; w++) mm = fmaxf(mm, red[w]);
        sm_max = mm;
    }
    __syncthreads();
    m = sm_max;

    float e0 = expf(la0 - m);
    float e1 = (t < LXd - 256) ? expf(la1 - m) : 0.f;
    float es = (t < 16) ? expf(slog[t] - m) : 0.f;
    float csum = e0 + e1 + es;
#pragma unroll
    for (int o = 16; o > 0; o >>= 1) csum += __shfl_xor_sync(0xffffffffu, csum, o);
    if (lane == 0) red[warp] = csum;
    __syncthreads();
    if (t == 0) {
        float s2 = 0.f;
        for (int w = 0; w < 8; w++) s2 += red[w];
        sm_sum = s2;
    }
    __syncthreads();
    const float invZ = 1.f / sm_sum;

    {   // attn_a weights -> bf16 hi/lo, layout [q][h*300+x]
        long o = (long)q * KAA + h * LXd + t;
        split1(e0 * invZ, &g_aah[o], &g_aal[o]);
        if (t < LXd - 256) split1(e1 * invZ, &g_aah[o + 256], &g_aal[o + 256]);
    }
    if (t < 16) sws[t] = es * invZ;
    if (warp == 0) {
        float ss = (t < 16) ? es * invZ : 0.f;
#pragma unroll
        for (int o = 16; o > 0; o >>= 1) ss += __shfl_xor_sync(0xffffffffu, ss, o);
        if (t == 0) g_ssum[q * Hd + h] = ss;
    }
    __syncthreads();

    float a = 0.f;
#pragma unroll
    for (int k = 0; k < 16; k++) a += sws[k] * skeys[k][t];
    long o = (long)(q * Hd + h) * Cd + t;
    split1(a, &g_aggh[o], &g_aggl[o]);
}

// out = q*headw_last + sum_h ssum*bv0f + 4 split-K partials
__global__ void combine_out(const float* __restrict__ query, float* __restrict__ out)
{
    int i = blockIdx.x * 256 + threadIdx.x;
    int c = i & 255, q = i >> 8;
    float v = query[i] * g_headw[Hd * Cd + c];
#pragma unroll
    for (int h = 0; h < Hd; h++) v += g_ssum[q * Hd + h] * g_bv0f[h * Cd + c];
    v += g_part[0][i] + g_part[1][i] + g_part[2][i] + g_part[3][i];
    out[i] = v;
}

// ---------------------------------------------------------------------------
extern "C" void kernel_launch(void* const* d_in, const int* in_sizes, int n_in,
                              void* d_out, int out_size)
{
    const float* query  = (const float*)d_in[0];
    const float* ref    = (const float*)d_in[1];
    const float* flat   = (const float*)d_in[2];
    const int*   iss    = (const int*)  d_in[3];
    const float* ak     = (const float*)d_in[4];
    const int*   lsi    = (const int*)  d_in[5];
    const float* W_off  = (const float*)d_in[6];
    const float* b_off  = (const float*)d_in[7];
    const float* W_attn = (const float*)d_in[8];
    const float* W_v    = (const float*)d_in[9];
    const float* b_v    = (const float*)d_in[10];
    const float* W_mix  = (const float*)d_in[11];
    float* out = (float*)d_out;

    float* p_off;
    cudaGetSymbolAddress((void**)&p_off, g_off);

    static int smem_set = 0;
    if (!smem_set) {
        cudaFuncSetAttribute(slog_mma,
                             cudaFuncAttributeMaxDynamicSharedMemorySize, SLOG_SMEM);
        smem_set = 1;
    }

    // operand conversions
    cvt_qf<<<(LQd * Cd + LEN * Cd) / 256, 256>>>(query, flat);
    cvt_akT<<<dim3(Cd / 32, 10), dim3(32, 8)>>>(ak);
    cvt_wts<<<2 * Hd * Cd * Cd / 256, 256>>>(W_attn, W_v);

    // off = query @ W_off^T ; sampling indices
    sgemm_tb<<<dim3(4, 32), 256>>>(query, Cd, W_off, Cd, p_off, Cd, LQd, Cd, Cd);
    loc_kernel<<<(LQd * Hd * Ld * Pd + 255) / 256, 256>>>(ref, b_off, iss, lsi);

    // P[h] = Wadd[h] @ akT (bf16x3, hi/lo split store), then attn_a logits
    P_gemm<<<dim3((LXd + 63) / 64, Cd / 128, Hd), 256, BF3_SMEM>>>();
    attn_gemm<<<dim3((LXd + 63) / 64, LQd / 128, Hd), 256, BF3_SMEM>>>();

    // scrambled attn_s logits (bf16x3 MMA)
    slog_mma<<<dim3(32, Ld, Hd), 256, SLOG_SMEM>>>(W_attn);

    // head mixing + value-side folds
    prep_headw<<<1, 256>>>(W_mix, b_v);
    v2t_gemm<<<dim3((LXd + 63) / 64, Cd / 128, Hd), 256, BF3_SMEM>>>();
    fold_v2t<<<dim3(Cd / 32, 10, Hd), dim3(32, 8)>>>(b_v);
    prep_fold<<<dim3(8, 8, Hd), dim3(32, 8)>>>(W_v);

    // gather + softmax + aggregation (emits bf16 hi/lo A-operands)
    fuse_kernel<<<dim3(LQd, Hd), 256>>>(flat);

    // output GEMMs: 4 split-K slabs in ONE launch
    out_gemm<<<dim3(Cd / 64, LQd / 128, 4), 256, BF3_SMEM>>>();

    combine_out<<<LQd * Cd / 256, 256>>>(query, out);
}

// round 15
// speedup vs baseline: 1.8412x; 1.3293x over previous
#include <cuda_runtime.h>
#include <cuda_bf16.h>
#include <math.h>

// Problem constants
constexpr int Cd  = 256;
constexpr int Hd  = 8;
constexpr int Ld  = 4;
constexpr int Pd  = 4;
constexpr int LQd = 2048;
constexpr int LXd = 300;
constexpr int LEN = 5440;            // input_flatten rows
constexpr int PLD = 304;             // padded ld for [.,300] panels
constexpr int KAA = Hd * LXd;        // 2400

// ---------------------------------------------------------------------------
// Scratch (device globals; no allocation allowed)
// ---------------------------------------------------------------------------
__device__ __align__(16) float g_offp[2][LQd * Cd];
__device__ __align__(16) int   g_lin[LQd * Hd * Ld * Pd];
__device__ __align__(16) float g_slog[LQd * Hd * 16];
__device__ __align__(16) float g_attn_a[LQd * KAA];         // logits fp32 [q][h*300+x]
__device__ __align__(16) float g_ssum[LQd * Hd];
__device__ __align__(16) float g_headw[(Hd + 1) * Cd];
__device__ __align__(16) float g_bv0f[Hd * Cd];
__device__ __align__(16) float g_v2t[Hd * Cd * PLD + 64];   // fp32 v2^T [h][c][x]
__device__ __align__(16) float g_part[4][LQd * Cd];

// bf16 hi/lo operand banks
__device__ __align__(16) __nv_bfloat16 g_qh[LQd * Cd],  g_ql[LQd * Cd];
__device__ __align__(16) __nv_bfloat16 g_fh[LEN * Cd],  g_fl[LEN * Cd];
__device__ __align__(16) __nv_bfloat16 g_akTh[Cd * PLD + 64], g_akTl[Cd * PLD + 64];
__device__ __align__(16) __nv_bfloat16 g_wah[Hd * Cd * Cd],  g_wal[Hd * Cd * Cd];   // Wadd
__device__ __align__(16) __nv_bfloat16 g_wv1h[Hd * Cd * Cd], g_wv1l[Hd * Cd * Cd];  // Wv1
__device__ __align__(16) __nv_bfloat16 g_Ph[Hd * Cd * PLD + 64], g_Pl[Hd * Cd * PLD + 64];
__device__ __align__(16) __nv_bfloat16 g_aah[LQd * KAA], g_aal[LQd * KAA];   // attn_a weights
__device__ __align__(16) __nv_bfloat16 g_aggh[LQd * Hd * Cd], g_aggl[LQd * Hd * Cd];
__device__ __align__(16) __nv_bfloat16 g_wv0h[Hd * Cd * Cd], g_wv0l[Hd * Cd * Cd]; // [h*256+e][c]
__device__ __align__(16) __nv_bfloat16 g_v2fh[Hd * LXd * Cd], g_v2fl[Hd * LXd * Cd]; // [h*300+x][c]

// ---------------------------------------------------------------------------
// Helpers
// ---------------------------------------------------------------------------
__device__ __forceinline__ unsigned smem_u32(const void* p) {
    return (unsigned)__cvta_generic_to_shared(p);
}
__device__ __forceinline__ void ldsm_x4(unsigned addr, unsigned& r0, unsigned& r1,
                                        unsigned& r2, unsigned& r3) {
    asm volatile("ldmatrix.sync.aligned.m8n8.x4.shared.b16 {%0,%1,%2,%3}, [%4];"
                 : "=r"(r0), "=r"(r1), "=r"(r2), "=r"(r3) : "r"(addr));
}
__device__ __forceinline__ void ldsm_x4_trans(unsigned addr, unsigned& r0, unsigned& r1,
                                              unsigned& r2, unsigned& r3) {
    asm volatile("ldmatrix.sync.aligned.m8n8.x4.trans.shared.b16 {%0,%1,%2,%3}, [%4];"
                 : "=r"(r0), "=r"(r1), "=r"(r2), "=r"(r3) : "r"(addr));
}
__device__ __forceinline__ void mma_bf16(float* c, const unsigned* a,
                                         unsigned b0, unsigned b1) {
    asm volatile(
        "mma.sync.aligned.m16n8k16.row.col.f32.bf16.bf16.f32 "
        "{%0,%1,%2,%3},{%4,%5,%6,%7},{%8,%9},{%0,%1,%2,%3};"
        : "+f"(c[0]), "+f"(c[1]), "+f"(c[2]), "+f"(c[3])
        : "r"(a[0]), "r"(a[1]), "r"(a[2]), "r"(a[3]), "r"(b0), "r"(b1));
}
__device__ __forceinline__ void split1(float f, __nv_bfloat16* h, __nv_bfloat16* l) {
    __nv_bfloat16 hh = __float2bfloat16(f);
    *h = hh;
    *l = __float2bfloat16(f - __bfloat162float(hh));
}
__device__ __forceinline__ void cp16(__nv_bfloat16* s, const __nv_bfloat16* g) {
    asm volatile("cp.async.cg.shared.global [%0], [%1], 16;"
                 :: "r"(smem_u32(s)), "l"(g) : "memory");
}
#define CP_COMMIT() asm volatile("cp.async.commit_group;" ::: "memory")
#define CP_WAIT0()  asm volatile("cp.async.wait_group 0;" ::: "memory")
#define CP_WAIT1()  asm volatile("cp.async.wait_group 1;" ::: "memory")

// ---------------------------------------------------------------------------
// Pipelined bf16x3 GEMM core: C[128 x 64 tile] = A @ B.
// A row-major [.,lda] hi/lo, B row-major [K][ldb] hi/lo. 256 thr, 8 warps
// (4m x 2n), warp tile 32x32. kLen % 32 == 0; M multiple of 128.
// 2-stage cp.async pipeline. SPLIT=true: hi/lo bf16 store to Ch/Cl.
// ---------------------------------------------------------------------------
constexpr int BF3_STG  = 14848;                 // per-stage elems (A 2x5120 + B 2x2304)
constexpr int BF3_SMEM = 2 * BF3_STG * 2;       // 59392 bytes

template <bool SPLIT>
__device__ __forceinline__ void bf3_tile(
    const __nv_bfloat16* __restrict__ Ahg, const __nv_bfloat16* __restrict__ Alg, int lda,
    const __nv_bfloat16* __restrict__ Bhg, const __nv_bfloat16* __restrict__ Blg, int ldb,
    float* __restrict__ C, __nv_bfloat16* __restrict__ Ch, __nv_bfloat16* __restrict__ Cl,
    int ldc, int N, int kLen)
{
    extern __shared__ __nv_bfloat16 smb[];
    const int tid = threadIdx.x, lane = tid & 31, warp = tid >> 5;
    const int wm = warp >> 1, wn = warp & 1;
    const int rowBase = blockIdx.y * 128, colBase = blockIdx.x * 64;

    auto issue = [&](int kt, int s) {
        __nv_bfloat16* Ah = smb + s * BF3_STG;
        __nv_bfloat16* Al = Ah + 5120;
        __nv_bfloat16* Bh = Al + 5120;
        __nv_bfloat16* Bl = Bh + 2304;
#pragma unroll
        for (int i = 0; i < 2; i++) {
            int idx = tid + i * 256;
            int r = idx >> 2, q = idx & 3;
            long off = (long)(rowBase + r) * lda + kt + q * 8;
            cp16(Ah + r * 40 + q * 8, Ahg + off);
            cp16(Al + r * 40 + q * 8, Alg + off);
        }
        {
            int r = tid >> 3, q = tid & 7;
            long off = (long)(kt + r) * ldb + colBase + q * 8;
            cp16(Bh + r * 72 + q * 8, Bhg + off);
            cp16(Bl + r * 72 + q * 8, Blg + off);
        }
        CP_COMMIT();
    };

    float acc[2][4][4] = {};
    const int n = kLen >> 5;
    issue(0, 0);
    for (int it = 0; it < n; it++) {
        if (it + 1 < n) { issue((it + 1) << 5, (it + 1) & 1); CP_WAIT1(); }
        else            { CP_WAIT0(); }
        __syncthreads();
        __nv_bfloat16* Ah = smb + (it & 1) * BF3_STG;
        __nv_bfloat16* Al = Ah + 5120;
        __nv_bfloat16* Bh = Al + 5120;
        __nv_bfloat16* Bl = Bh + 2304;
#pragma unroll
        for (int kk = 0; kk < 32; kk += 16) {
            unsigned ah[2][4], al[2][4];
#pragma unroll
            for (int mi = 0; mi < 2; mi++) {
                int rr = wm * 32 + mi * 16 + (lane & 15);
                int cc = kk + (lane >> 4) * 8;
                ldsm_x4(smem_u32(&Ah[rr * 40 + cc]), ah[mi][0], ah[mi][1], ah[mi][2], ah[mi][3]);
                ldsm_x4(smem_u32(&Al[rr * 40 + cc]), al[mi][0], al[mi][1], al[mi][2], al[mi][3]);
            }
#pragma unroll
            for (int nb = 0; nb < 2; nb++) {
                unsigned bh[4], bl[4];
                int rr = kk + (lane & 15);
                int cc = wn * 32 + nb * 16 + (lane >> 4) * 8;
                ldsm_x4_trans(smem_u32(&Bh[rr * 72 + cc]), bh[0], bh[1], bh[2], bh[3]);
                ldsm_x4_trans(smem_u32(&Bl[rr * 72 + cc]), bl[0], bl[1], bl[2], bl[3]);
#pragma unroll
                for (int mi = 0; mi < 2; mi++)
#pragma unroll
                    for (int t = 0; t < 2; t++) {
                        int ni = nb * 2 + t;
                        mma_bf16(acc[mi][ni], ah[mi], bh[t * 2], bh[t * 2 + 1]);
                        mma_bf16(acc[mi][ni], ah[mi], bl[t * 2], bl[t * 2 + 1]);
                        mma_bf16(acc[mi][ni], al[mi], bh[t * 2], bh[t * 2 + 1]);
                    }
            }
        }
        __syncthreads();
    }
    const int g = lane >> 2, qp = lane & 3;
#pragma unroll
    for (int mi = 0; mi < 2; mi++)
#pragma unroll
        for (int ni = 0; ni < 4; ni++)
#pragma unroll
            for (int ch = 0; ch < 2; ch++) {
                int gr = rowBase + wm * 32 + mi * 16 + g + ch * 8;
                int gc = colBase + wn * 32 + ni * 8 + qp * 2;
                if (gc < N) {
                    if (SPLIT) {
                        long o = (long)gr * ldc + gc;
                        split1(acc[mi][ni][ch * 2],     &Ch[o],     &Cl[o]);
                        if (gc + 1 < N)
                            split1(acc[mi][ni][ch * 2 + 1], &Ch[o + 1], &Cl[o + 1]);
                    } else {
                        *(float2*)&C[(long)gr * ldc + gc] =
                            make_float2(acc[mi][ni][ch * 2], acc[mi][ni][ch * 2 + 1]);
                    }
                }
            }
}

// P[h] = Wadd[h] @ akT  -> hi/lo split store [h][c][PLD]
__global__ __launch_bounds__(256) void P_gemm()
{
    int h = blockIdx.z;
    bf3_tile<true>(g_wah + (long)h * Cd * Cd, g_wal + (long)h * Cd * Cd, Cd,
                   g_akTh, g_akTl, PLD,
                   nullptr, g_Ph + (long)h * Cd * PLD, g_Pl + (long)h * Cd * PLD,
                   PLD, LXd, Cd);
}

// v2^T[h] = Wv1[h] @ akT  -> fp32 [h][c][PLD]
__global__ __launch_bounds__(256) void v2t_gemm()
{
    int h = blockIdx.z;
    bf3_tile<false>(g_wv1h + (long)h * Cd * Cd, g_wv1l + (long)h * Cd * Cd, Cd,
                    g_akTh, g_akTl, PLD,
                    g_v2t + (long)h * Cd * PLD, nullptr, nullptr, PLD, LXd, Cd);
}

// attn_a logits: query @ P[h]
__global__ __launch_bounds__(256) void attn_gemm()
{
    int h = blockIdx.z;
    bf3_tile<false>(g_qh, g_ql, Cd,
                    g_Ph + (long)h * Cd * PLD, g_Pl + (long)h * Cd * PLD, PLD,
                    g_attn_a + h * LXd, nullptr, nullptr, KAA, LXd, Cd);
}

// output GEMM partial slabs (split-K, 4 slabs in one launch)
__global__ __launch_bounds__(256) void out_gemm()
{
    int z = blockIdx.z;
    const __nv_bfloat16 *Ahg, *Alg, *Bhg, *Blg;
    int lda, kOff, kLen;
    if (z < 2) {
        Ahg = g_aggh; Alg = g_aggl; Bhg = g_wv0h; Blg = g_wv0l;
        lda = Hd * Cd; kOff = z * 1024; kLen = 1024;
    } else {
        Ahg = g_aah;  Alg = g_aal;  Bhg = g_v2fh; Blg = g_v2fl;
        lda = KAA; kOff = (z - 2) * 1216; kLen = (z == 2) ? 1216 : 1184;
    }
    bf3_tile<false>(Ahg + kOff, Alg + kOff, lda,
                    Bhg + (long)kOff * Cd, Blg + (long)kOff * Cd, Cd,
                    g_part[z], nullptr, nullptr, Cd, Cd, kLen);
}

// ---------------------------------------------------------------------------
// Scrambled attn_s logits via pipelined bf16x3 MMA.
// Block (r,l,h): M[j,e] = sum_c' qf[r+32j,c'] * flat[slin[c']][e]  (64x256x256)
// then logit[p,j] = Ws[h,l,p*64+j,:] . M[j,:]
// ---------------------------------------------------------------------------
constexpr int SLOG_STG  = 22016;                        // per-stage elems
constexpr int SLOG_SMEM = 2 * SLOG_STG * 2;             // 88064 (>= Ms 68608)

__global__ __launch_bounds__(256) void slog_mma(const float* __restrict__ W_attn)
{
    extern __shared__ char sm[];
    __nv_bfloat16* smb = (__nv_bfloat16*)sm;
    float* Ms = (float*)sm;                              // [64][268] overlays stages
    __shared__ int slin[256];

    const int r = blockIdx.x, l = blockIdx.y, h = blockIdx.z;
    const int tid = threadIdx.x, lane = tid & 31, warp = tid >> 5;
    const int wm = warp & 1, wn = warp >> 1;
    const int p2 = r >> 3, b = r & 7;
    slin[tid] = g_lin[((256 * b + tid) * Hd + h) * 16 + l * 4 + p2];
    __syncthreads();

    auto issue = [&](int ck, int s) {
        __nv_bfloat16* Ah = smb + s * SLOG_STG;
        __nv_bfloat16* Al = Ah + 2560;
        __nv_bfloat16* Bh = Al + 2560;
        __nv_bfloat16* Bl = Bh + 8448;
        {
            int j = tid >> 2, q = tid & 3;
            long off = (long)(r + 32 * j) * Cd + ck + q * 8;
            cp16(Ah + j * 40 + q * 8, g_qh + off);
            cp16(Al + j * 40 + q * 8, g_ql + off);
        }
#pragma unroll
        for (int i = 0; i < 4; i++) {
            int idx = tid + i * 256;
            int kr = idx >> 5, q = idx & 31;
            long off = (long)slin[ck + kr] * Cd + q * 8;
            cp16(Bh + kr * 264 + q * 8, g_fh + off);
            cp16(Bl + kr * 264 + q * 8, g_fl + off);
        }
        CP_COMMIT();
    };

    float acc[2][8][4] = {};
    issue(0, 0);
    for (int it = 0; it < 8; it++) {
        if (it + 1 < 8) { issue((it + 1) << 5, (it + 1) & 1); CP_WAIT1(); }
        else            { CP_WAIT0(); }
        __syncthreads();
        __nv_bfloat16* Ah = smb + (it & 1) * SLOG_STG;
        __nv_bfloat16* Al = Ah + 2560;
        __nv_bfloat16* Bh = Al + 2560;
        __nv_bfloat16* Bl = Bh + 8448;
#pragma unroll
        for (int kk = 0; kk < 32; kk += 16) {
            unsigned ah[2][4], al[2][4];
#pragma unroll
            for (int mi = 0; mi < 2; mi++) {
                int rr = wm * 32 + mi * 16 + (lane & 15);
                int cc = kk + (lane >> 4) * 8;
                ldsm_x4(smem_u32(&Ah[rr * 40 + cc]), ah[mi][0], ah[mi][1], ah[mi][2], ah[mi][3]);
                ldsm_x4(smem_u32(&Al[rr * 40 + cc]), al[mi][0], al[mi][1], al[mi][2], al[mi][3]);
            }
#pragma unroll
            for (int nb = 0; nb < 4; nb++) {
                unsigned bh[4], bl[4];
                int rr = kk + (lane & 15);
                int cc = wn * 64 + nb * 16 + (lane >> 4) * 8;
                ldsm_x4_trans(smem_u32(&Bh[rr * 264 + cc]), bh[0], bh[1], bh[2], bh[3]);
                ldsm_x4_trans(smem_u32(&Bl[rr * 264 + cc]), bl[0], bl[1], bl[2], bl[3]);
#pragma unroll
                for (int mi = 0; mi < 2; mi++)
#pragma unroll
                    for (int t = 0; t < 2; t++) {
                        int ni = nb * 2 + t;
                        mma_bf16(acc[mi][ni], ah[mi], bh[t * 2], bh[t * 2 + 1]);
                        mma_bf16(acc[mi][ni], ah[mi], bl[t * 2], bl[t * 2 + 1]);
                        mma_bf16(acc[mi][ni], al[mi], bh[t * 2], bh[t * 2 + 1]);
                    }
            }
        }
        __syncthreads();
    }

    // acc -> Ms (overlays stage buffers; safe after the loop's trailing barrier)
    const int g = lane >> 2, qp = lane & 3;
#pragma unroll
    for (int mi = 0; mi < 2; mi++)
#pragma unroll
        for (int ni = 0; ni < 8; ni++)
#pragma unroll
            for (int ch = 0; ch < 2; ch++) {
                int row = wm * 32 + mi * 16 + g + ch * 8;
                int col = wn * 64 + ni * 8 + qp * 2;
                *(float2*)&Ms[row * 268 + col] =
                    make_float2(acc[mi][ni][ch * 2], acc[mi][ni][ch * 2 + 1]);
            }
    __syncthreads();

    // stage 2: one logit per thread
    int p = tid >> 6, j = tid & 63;
    int cstar = p * 64 + j;
    const float4* w4 = (const float4*)(W_attn + ((long)(h * Ld + l) * Cd + cstar) * Cd);
    const float* mrow = Ms + j * 268;
    float s = 0.f;
#pragma unroll 4
    for (int e4 = 0; e4 < 64; e4++) {
        float4 w = w4[e4];
        s += w.x * mrow[e4 * 4] + w.y * mrow[e4 * 4 + 1]
           + w.z * mrow[e4 * 4 + 2] + w.w * mrow[e4 * 4 + 3];
    }
    int q = r + 32 * j;
    g_slog[(q * Hd + h) * 16 + l * 4 + p] = s;
}

// ---------------------------------------------------------------------------
// fp32 off-projection (index-sensitive, stays fp32): split-K, 2 slabs.
// off_partial[z] = query @ W_off^T over K slab z.
// ---------------------------------------------------------------------------
__global__ void off_gemm(const float* __restrict__ A, const float* __restrict__ B)
{
    __shared__ float As[16][68];
    __shared__ float Bs[16][68];
    const int tid = threadIdx.x;
    const int kOff = blockIdx.z * 128;
    float* Cm = g_offp[blockIdx.z];
    const int rowBase = blockIdx.y * 64, colBase = blockIdx.x * 64;
    const int tr = (tid >> 4) * 4, tc = (tid & 15) * 4;
    float acc[4][4] = {};

    for (int kt = 0; kt < 128; kt += 16) {
#pragma unroll
        for (int i = 0; i < 4; i++) {
            int idx = tid + i * 256;
            int ar = idx >> 4, ac = idx & 15;
            As[ac][ar] = A[(long)(rowBase + ar) * Cd + kOff + kt + ac];
        }
#pragma unroll
        for (int i = 0; i < 4; i++) {
            int idx = tid + i * 256;
            int bn = idx >> 4, bk = idx & 15;
            Bs[bk][bn] = B[(long)(colBase + bn) * Cd + kOff + kt + bk];
        }
        __syncthreads();
#pragma unroll
        for (int k = 0; k < 16; k++) {
            float4 av = *(const float4*)&As[k][tr];
            float4 bv = *(const float4*)&Bs[k][tc];
            float a[4] = {av.x, av.y, av.z, av.w};
            float b[4] = {bv.x, bv.y, bv.z, bv.w};
#pragma unroll
            for (int i = 0; i < 4; i++)
#pragma unroll
                for (int j = 0; j < 4; j++) acc[i][j] += a[i] * b[j];
        }
        __syncthreads();
    }
#pragma unroll
    for (int i = 0; i < 4; i++)
#pragma unroll
        for (int j = 0; j < 4; j++)
            Cm[(long)(rowBase + tr + i) * Cd + colBase + tc + j] = acc[i][j];
}

// ---------------------------------------------------------------------------
// Conversion / prep kernels
// ---------------------------------------------------------------------------
__global__ void cvt_qf(const float* __restrict__ query, const float* __restrict__ flat)
{
    long i = (long)blockIdx.x * 256 + threadIdx.x;
    if (i < (long)LQd * Cd) {
        split1(query[i], &g_qh[i], &g_ql[i]);
    } else {
        long j = i - (long)LQd * Cd;
        split1(flat[j], &g_fh[j], &g_fl[j]);
    }
}

// ak [300][256] -> akT hi/lo [256][304] (zero-padded cols 300..303)
__global__ void cvt_akT(const float* __restrict__ ak)
{
    __shared__ float t[32][33];
    int k0 = blockIdx.x * 32;
    int x0 = blockIdx.y * 32;
    int x = threadIdx.x, y = threadIdx.y;
    for (int i = 0; i < 32; i += 8) {
        int xx = x0 + y + i;
        t[y + i][x] = (xx < LXd) ? ak[(long)xx * Cd + k0 + x] : 0.f;
    }
    __syncthreads();
    for (int i = 0; i < 32; i += 8) {
        int kk = k0 + y + i;
        int xx = x0 + x;
        if (xx < PLD) {
            long o = (long)kk * PLD + xx;
            split1(t[x][y + i], &g_akTh[o], &g_akTl[o]);
        }
    }
}

// Wadd (W_attn[4h+4]) and Wv1 (W_v[2h+1]) -> bf16 hi/lo
__global__ void cvt_wts(const float* __restrict__ W_attn, const float* __restrict__ W_v)
{
    long i = (long)blockIdx.x * 256 + threadIdx.x;
    const long half = (long)Hd * Cd * Cd;
    if (i < half) {
        int h = (int)(i >> 16);
        long rem = i & 65535;
        split1(W_attn[((long)(4 * h + 4) << 16) + rem], &g_wah[i], &g_wal[i]);
    } else {
        long j = i - half;
        int h = (int)(j >> 16);
        long rem = j & 65535;
        split1(W_v[((long)(2 * h + 1) << 16) + rem], &g_wv1h[j], &g_wv1l[j]);
    }
}

__global__ void prep_headw(const float* __restrict__ W_mix, const float* __restrict__ b_v)
{
    int c = threadIdx.x;
    float m = -1e30f;
    for (int j = 0; j <= Hd; j++) m = fmaxf(m, W_mix[c * (Hd + 1) + j]);
    float e[Hd + 1];
    float Z = 0.f;
    for (int j = 0; j <= Hd; j++) { e[j] = expf(W_mix[c * (Hd + 1) + j] - m); Z += e[j]; }
    float invZ = 1.f / Z;
    for (int j = 0; j <= Hd; j++) g_headw[j * Cd + c] = e[j] * invZ;
    for (int h = 0; h < Hd; h++)  g_bv0f[h * Cd + c] = e[h] * invZ * b_v[(2 * h) * Cd + c];
}

// wv0ft[h][e][c] = head_w[h][c] * W_v[2h][c][e]  -> bf16 hi/lo
__global__ void prep_fold(const float* __restrict__ W_v)
{
    __shared__ float t[32][33];
    int h = blockIdx.z;
    int e0 = blockIdx.x * 32, c0 = blockIdx.y * 32;
    int x = threadIdx.x, y = threadIdx.y;
    for (int i = 0; i < 32; i += 8) {
        int cc = c0 + y + i;
        t[y + i][x] = W_v[((long)(2 * h) * Cd + cc) * Cd + e0 + x];
    }
    __syncthreads();
    for (int i = 0; i < 32; i += 8) {
        int ee = e0 + y + i;
        int cc = c0 + x;
        float v = g_headw[h * Cd + cc] * t[x][y + i];
        long o = ((long)h * Cd + ee) * Cd + cc;
        split1(v, &g_wv0h[o], &g_wv0l[o]);
    }
}

// v2f[h*300+x][c] = head_w[h][c]*(v2t[h][c][x] + bv1[h][c]) -> bf16 hi/lo
__global__ void fold_v2t(const float* __restrict__ b_v)
{
    __shared__ float t[32][33];
    int h = blockIdx.z;
    int c0 = blockIdx.x * 32, x0 = blockIdx.y * 32;
    int x = threadIdx.x, y = threadIdx.y;
    for (int i = 0; i < 32; i += 8) {
        int cc = c0 + y + i;
        t[y + i][x] = g_v2t[((long)h * Cd + cc) * PLD + x0 + x];
    }
    __syncthreads();
    for (int i = 0; i < 32; i += 8) {
        int xx = x0 + y + i;
        int cc = c0 + x;
        if (xx < LXd) {
            float v = g_headw[h * Cd + cc] * (t[x][y + i] + b_v[(2 * h + 1) * Cd + cc]);
            long o = (long)(h * LXd + xx) * Cd + cc;
            split1(v, &g_v2fh[o], &g_v2fl[o]);
        }
    }
}

__global__ void loc_kernel(const float* __restrict__ ref, const float* __restrict__ b_off,
                           const int* __restrict__ iss, const int* __restrict__ lsi)
{
    int id = blockIdx.x * 256 + threadIdx.x;
    if (id >= LQd * Hd * Ld * Pd) return;
    int q = id >> 7;
    int r = id & 127;
    int hh = r >> 4;
    int l = (r >> 2) & 3;
    int p = r & 3;
    int j = ((hh * Ld + l) * Pd + p) * 2;
    float off0 = g_offp[0][q * Cd + j]     + g_offp[1][q * Cd + j]     + b_off[j];
    float off1 = g_offp[0][q * Cd + j + 1] + g_offp[1][q * Cd + j + 1] + b_off[j + 1];
    int W0 = iss[l * 2], W1 = iss[l * 2 + 1];
    float ref0 = ref[(q * Ld + l) * 2];
    float ref1 = ref[(q * Ld + l) * 2 + 1];
    float loc0 = ref0 + off0 / (float)W1;
    float loc1 = ref1 + off1 / (float)W0;
    loc0 = fminf(fmaxf(loc0, 0.f), 0.999f);
    loc1 = fminf(fmaxf(loc1, 0.f), 0.999f);
    int ix = (int)(loc0 * (float)W0);
    int iy = (int)(loc1 * (float)W1);
    g_lin[id] = ix + iy * W0 + lsi[l];
}

// ---------------------------------------------------------------------------
// Merged softmax + aggregation: one block per q, one warp per head.
// ---------------------------------------------------------------------------
__global__ __launch_bounds__(256) void fuse_kernel(const float* __restrict__ flat)
{
    __shared__ float sws[Hd][16];
    __shared__ int   slinS[Hd][16];

    const int q = blockIdx.x;
    const int w = threadIdx.x >> 5, lane = threadIdx.x & 31;
    const int h = w;
    const int base16 = (q * Hd + h) * 16;

    float lg16 = -1e30f;
    if (lane < 16) {
        slinS[w][lane] = g_lin[base16 + lane];
        lg16 = g_slog[base16 + lane];
    }
    const long arow = (long)q * KAA + h * LXd;
    float la[10];
#pragma unroll
    for (int j = 0; j < 9; j++) la[j] = g_attn_a[arow + lane + 32 * j];
    la[9] = (lane < 12) ? g_attn_a[arow + 288 + lane] : -1e30f;

    float m = lg16;
#pragma unroll
    for (int j = 0; j < 10; j++) m = fmaxf(m, la[j]);
#pragma unroll
    for (int o = 16; o > 0; o >>= 1) m = fmaxf(m, __shfl_xor_sync(0xffffffffu, m, o));

    float e[10];
    float csum = 0.f;
#pragma unroll
    for (int j = 0; j < 10; j++) { e[j] = expf(la[j] - m); csum += e[j]; }
    float es = (lane < 16) ? expf(lg16 - m) : 0.f;
    csum += es;
#pragma unroll
    for (int o = 16; o > 0; o >>= 1) csum += __shfl_xor_sync(0xffffffffu, csum, o);
    const float invZ = 1.f / csum;

#pragma unroll
    for (int j = 0; j < 9; j++) {
        long o2 = arow + lane + 32 * j;
        split1(e[j] * invZ, &g_aah[o2], &g_aal[o2]);
    }
    if (lane < 12) {
        long o2 = arow + 288 + lane;
        split1(e[9] * invZ, &g_aah[o2], &g_aal[o2]);
    }

    float wk = es * invZ;
    if (lane < 16) sws[w][lane] = wk;
    float ss = wk;
#pragma unroll
    for (int o = 16; o > 0; o >>= 1) ss += __shfl_xor_sync(0xffffffffu, ss, o);
    if (lane == 0) g_ssum[q * Hd + h] = ss;
    __syncwarp();

    float agg[8] = {};
#pragma unroll
    for (int k = 0; k < 16; k++) {
        const float* row = flat + (long)slinS[w][k] * Cd + lane;
        float wv = sws[w][k];
#pragma unroll
        for (int j = 0; j < 8; j++) agg[j] += wv * row[32 * j];
    }
    const long ob = (long)(q * Hd + h) * Cd + lane;
#pragma unroll
    for (int j = 0; j < 8; j++) split1(agg[j], &g_aggh[ob + 32 * j], &g_aggl[ob + 32 * j]);
}

// out = q*headw_last + sum_h ssum*bv0f + 4 split-K partials
__global__ void combine_out(const float* __restrict__ query, float* __restrict__ out)
{
    int i = blockIdx.x * 256 + threadIdx.x;
    int c = i & 255, q = i >> 8;
    float v = query[i] * g_headw[Hd * Cd + c];
#pragma unroll
    for (int h = 0; h < Hd; h++) v += g_ssum[q * Hd + h] * g_bv0f[h * Cd + c];
    v += g_part[0][i] + g_part[1][i] + g_part[2][i] + g_part[3][i];
    out[i] = v;
}

// ---------------------------------------------------------------------------
extern "C" void kernel_launch(void* const* d_in, const int* in_sizes, int n_in,
                              void* d_out, int out_size)
{
    const float* query  = (const float*)d_in[0];
    const float* ref    = (const float*)d_in[1];
    const float* flat   = (const float*)d_in[2];
    const int*   iss    = (const int*)  d_in[3];
    const float* ak     = (const float*)d_in[4];
    const int*   lsi    = (const int*)  d_in[5];
    const float* W_off  = (const float*)d_in[6];
    const float* b_off  = (const float*)d_in[7];
    const float* W_attn = (const float*)d_in[8];
    const float* W_v    = (const float*)d_in[9];
    const float* b_v    = (const float*)d_in[10];
    const float* W_mix  = (const float*)d_in[11];
    float* out = (float*)d_out;

    static int smem_set = 0;
    if (!smem_set) {
        cudaFuncSetAttribute(slog_mma,
                             cudaFuncAttributeMaxDynamicSharedMemorySize, SLOG_SMEM);
        cudaFuncSetAttribute(P_gemm,
                             cudaFuncAttributeMaxDynamicSharedMemorySize, BF3_SMEM);
        cudaFuncSetAttribute(v2t_gemm,
                             cudaFuncAttributeMaxDynamicSharedMemorySize, BF3_SMEM);
        cudaFuncSetAttribute(attn_gemm,
                             cudaFuncAttributeMaxDynamicSharedMemorySize, BF3_SMEM);
        cudaFuncSetAttribute(out_gemm,
                             cudaFuncAttributeMaxDynamicSharedMemorySize, BF3_SMEM);
        smem_set = 1;
    }

    // operand conversions
    cvt_qf<<<(LQd * Cd + LEN * Cd) / 256, 256>>>(query, flat);
    cvt_akT<<<dim3(Cd / 32, 10), dim3(32, 8)>>>(ak);
    cvt_wts<<<2 * Hd * Cd * Cd / 256, 256>>>(W_attn, W_v);

    // off = query @ W_off^T (fp32, split-K 2 slabs) ; sampling indices
    off_gemm<<<dim3(4, 32, 2), 256>>>(query, W_off);
    loc_kernel<<<(LQd * Hd * Ld * Pd + 255) / 256, 256>>>(ref, b_off, iss, lsi);

    // P[h] = Wadd[h] @ akT (hi/lo split store), then attn_a logits
    P_gemm<<<dim3((LXd + 63) / 64, Cd / 128, Hd), 256, BF3_SMEM>>>();
    attn_gemm<<<dim3((LXd + 63) / 64, LQd / 128, Hd), 256, BF3_SMEM>>>();

    // scrambled attn_s logits (pipelined bf16x3 MMA)
    slog_mma<<<dim3(32, Ld, Hd), 256, SLOG_SMEM>>>(W_attn);

    // head mixing + value-side folds
    prep_headw<<<1, 256>>>(W_mix, b_v);
    v2t_gemm<<<dim3((LXd + 63) / 64, Cd / 128, Hd), 256, BF3_SMEM>>>();
    fold_v2t<<<dim3(Cd / 32, 10, Hd), dim3(32, 8)>>>(b_v);
    prep_fold<<<dim3(8, 8, Hd), dim3(32, 8)>>>(W_v);

    // softmax + aggregation (merged: block per q, warp per head)
    fuse_kernel<<<LQd, 256>>>(flat);

    // output GEMMs: 4 split-K slabs in ONE launch
    out_gemm<<<dim3(Cd / 64, LQd / 128, 4), 256, BF3_SMEM>>>();

    combine_out<<<LQd * Cd / 256, 256>>>(query, out);
}

// round 17
// speedup vs baseline: 1.8890x; 1.0259x over previous
#include <cuda_runtime.h>
#include <cuda_bf16.h>
#include <math.h>

// Problem constants
constexpr int Cd  = 256;
constexpr int Hd  = 8;
constexpr int Ld  = 4;
constexpr int Pd  = 4;
constexpr int LQd = 2048;
constexpr int LXd = 300;
constexpr int LEN = 5440;            // input_flatten rows
constexpr int PLD = 304;             // padded ld for [.,300] panels
constexpr int KAA = Hd * LXd;        // 2400

// ---------------------------------------------------------------------------
// Scratch (device globals; no allocation allowed)
// ---------------------------------------------------------------------------
__device__ __align__(16) float g_offp[4][LQd * Cd];
__device__ __align__(16) int   g_lin[LQd * Hd * Ld * Pd];
__device__ __align__(16) float g_slog[LQd * Hd * 16];
__device__ __align__(16) float g_attn_a[LQd * KAA];         // logits fp32 [q][h*300+x]
__device__ __align__(16) float g_ssum[LQd * Hd];
__device__ __align__(16) float g_headw[(Hd + 1) * Cd];
__device__ __align__(16) float g_bv0f[Hd * Cd];
__device__ __align__(16) float g_v2t[Hd * Cd * PLD + 64];   // fp32 v2^T [h][c][x]
__device__ __align__(16) float g_part[8][LQd * Cd];

// bf16 hi/lo operand banks
__device__ __align__(16) __nv_bfloat16 g_qh[LQd * Cd],  g_ql[LQd * Cd];
__device__ __align__(16) __nv_bfloat16 g_fh[LEN * Cd],  g_fl[LEN * Cd];
__device__ __align__(16) __nv_bfloat16 g_akTh[Cd * PLD + 64], g_akTl[Cd * PLD + 64];
__device__ __align__(16) __nv_bfloat16 g_wah[Hd * Cd * Cd],  g_wal[Hd * Cd * Cd];   // Wadd
__device__ __align__(16) __nv_bfloat16 g_wv1h[Hd * Cd * Cd], g_wv1l[Hd * Cd * Cd];  // Wv1
__device__ __align__(16) __nv_bfloat16 g_Ph[Hd * Cd * PLD + 64], g_Pl[Hd * Cd * PLD + 64];
__device__ __align__(16) __nv_bfloat16 g_aah[LQd * KAA], g_aal[LQd * KAA];   // attn_a weights
__device__ __align__(16) __nv_bfloat16 g_aggh[LQd * Hd * Cd], g_aggl[LQd * Hd * Cd];
__device__ __align__(16) __nv_bfloat16 g_wv0h[Hd * Cd * Cd], g_wv0l[Hd * Cd * Cd]; // [h*256+e][c]
__device__ __align__(16) __nv_bfloat16 g_v2fh[Hd * LXd * Cd], g_v2fl[Hd * LXd * Cd]; // [h*300+x][c]

// ---------------------------------------------------------------------------
// Helpers
// ---------------------------------------------------------------------------
__device__ __forceinline__ unsigned smem_u32(const void* p) {
    return (unsigned)__cvta_generic_to_shared(p);
}
__device__ __forceinline__ void ldsm_x4(unsigned addr, unsigned& r0, unsigned& r1,
                                        unsigned& r2, unsigned& r3) {
    asm volatile("ldmatrix.sync.aligned.m8n8.x4.shared.b16 {%0,%1,%2,%3}, [%4];"
                 : "=r"(r0), "=r"(r1), "=r"(r2), "=r"(r3) : "r"(addr));
}
__device__ __forceinline__ void ldsm_x4_trans(unsigned addr, unsigned& r0, unsigned& r1,
                                              unsigned& r2, unsigned& r3) {
    asm volatile("ldmatrix.sync.aligned.m8n8.x4.trans.shared.b16 {%0,%1,%2,%3}, [%4];"
                 : "=r"(r0), "=r"(r1), "=r"(r2), "=r"(r3) : "r"(addr));
}
__device__ __forceinline__ void mma_bf16(float* c, const unsigned* a,
                                         unsigned b0, unsigned b1) {
    asm volatile(
        "mma.sync.aligned.m16n8k16.row.col.f32.bf16.bf16.f32 "
        "{%0,%1,%2,%3},{%4,%5,%6,%7},{%8,%9},{%0,%1,%2,%3};"
        : "+f"(c[0]), "+f"(c[1]), "+f"(c[2]), "+f"(c[3])
        : "r"(a[0]), "r"(a[1]), "r"(a[2]), "r"(a[3]), "r"(b0), "r"(b1));
}
__device__ __forceinline__ void split1(float f, __nv_bfloat16* h, __nv_bfloat16* l) {
    __nv_bfloat16 hh = __float2bfloat16(f);
    *h = hh;
    *l = __float2bfloat16(f - __bfloat162float(hh));
}
__device__ __forceinline__ void cp16(__nv_bfloat16* s, const __nv_bfloat16* g) {
    asm volatile("cp.async.cg.shared.global [%0], [%1], 16;"
                 :: "r"(smem_u32(s)), "l"(g) : "memory");
}
#define CP_COMMIT() asm volatile("cp.async.commit_group;" ::: "memory")
#define CP_WAIT0()  asm volatile("cp.async.wait_group 0;" ::: "memory")
#define CP_WAIT1()  asm volatile("cp.async.wait_group 1;" ::: "memory")

// ---------------------------------------------------------------------------
// Pipelined bf16x3 GEMM core: C[128 x 64 tile] = A @ B.
// A row-major [.,lda] hi/lo, B row-major [K][ldb] hi/lo. 256 thr, 8 warps
// (4m x 2n), warp tile 32x32. kLen % 32 == 0; M multiple of 128.
// 2-stage cp.async pipeline. SPLIT=true: hi/lo bf16 store to Ch/Cl.
// ---------------------------------------------------------------------------
constexpr int BF3_STG  = 14848;                 // per-stage elems (A 2x5120 + B 2x2304)
constexpr int BF3_SMEM = 2 * BF3_STG * 2;       // 59392 bytes

template <bool SPLIT>
__device__ __forceinline__ void bf3_tile(
    const __nv_bfloat16* __restrict__ Ahg, const __nv_bfloat16* __restrict__ Alg, int lda,
    const __nv_bfloat16* __restrict__ Bhg, const __nv_bfloat16* __restrict__ Blg, int ldb,
    float* __restrict__ C, __nv_bfloat16* __restrict__ Ch, __nv_bfloat16* __restrict__ Cl,
    int ldc, int N, int kLen)
{
    extern __shared__ __nv_bfloat16 smb[];
    const int tid = threadIdx.x, lane = tid & 31, warp = tid >> 5;
    const int wm = warp >> 1, wn = warp & 1;
    const int rowBase = blockIdx.y * 128, colBase = blockIdx.x * 64;

    auto issue = [&](int kt, int s) {
        __nv_bfloat16* Ah = smb + s * BF3_STG;
        __nv_bfloat16* Al = Ah + 5120;
        __nv_bfloat16* Bh = Al + 5120;
        __nv_bfloat16* Bl = Bh + 2304;
#pragma unroll
        for (int i = 0; i < 2; i++) {
            int idx = tid + i * 256;
            int r = idx >> 2, q = idx & 3;
            long off = (long)(rowBase + r) * lda + kt + q * 8;
            cp16(Ah + r * 40 + q * 8, Ahg + off);
            cp16(Al + r * 40 + q * 8, Alg + off);
        }
        {
            int r = tid >> 3, q = tid & 7;
            long off = (long)(kt + r) * ldb + colBase + q * 8;
            cp16(Bh + r * 72 + q * 8, Bhg + off);
            cp16(Bl + r * 72 + q * 8, Blg + off);
        }
        CP_COMMIT();
    };

    float acc[2][4][4] = {};
    const int n = kLen >> 5;
    issue(0, 0);
    for (int it = 0; it < n; it++) {
        if (it + 1 < n) { issue((it + 1) << 5, (it + 1) & 1); CP_WAIT1(); }
        else            { CP_WAIT0(); }
        __syncthreads();
        __nv_bfloat16* Ah = smb + (it & 1) * BF3_STG;
        __nv_bfloat16* Al = Ah + 5120;
        __nv_bfloat16* Bh = Al + 5120;
        __nv_bfloat16* Bl = Bh + 2304;
#pragma unroll
        for (int kk = 0; kk < 32; kk += 16) {
            unsigned ah[2][4], al[2][4];
#pragma unroll
            for (int mi = 0; mi < 2; mi++) {
                int rr = wm * 32 + mi * 16 + (lane & 15);
                int cc = kk + (lane >> 4) * 8;
                ldsm_x4(smem_u32(&Ah[rr * 40 + cc]), ah[mi][0], ah[mi][1], ah[mi][2], ah[mi][3]);
                ldsm_x4(smem_u32(&Al[rr * 40 + cc]), al[mi][0], al[mi][1], al[mi][2], al[mi][3]);
            }
#pragma unroll
            for (int nb = 0; nb < 2; nb++) {
                unsigned bh[4], bl[4];
                int rr = kk + (lane & 15);
                int cc = wn * 32 + nb * 16 + (lane >> 4) * 8;
                ldsm_x4_trans(smem_u32(&Bh[rr * 72 + cc]), bh[0], bh[1], bh[2], bh[3]);
                ldsm_x4_trans(smem_u32(&Bl[rr * 72 + cc]), bl[0], bl[1], bl[2], bl[3]);
#pragma unroll
                for (int mi = 0; mi < 2; mi++)
#pragma unroll
                    for (int t = 0; t < 2; t++) {
                        int ni = nb * 2 + t;
                        mma_bf16(acc[mi][ni], ah[mi], bh[t * 2], bh[t * 2 + 1]);
                        mma_bf16(acc[mi][ni], ah[mi], bl[t * 2], bl[t * 2 + 1]);
                        mma_bf16(acc[mi][ni], al[mi], bh[t * 2], bh[t * 2 + 1]);
                    }
            }
        }
        __syncthreads();
    }
    const int g = lane >> 2, qp = lane & 3;
#pragma unroll
    for (int mi = 0; mi < 2; mi++)
#pragma unroll
        for (int ni = 0; ni < 4; ni++)
#pragma unroll
            for (int ch = 0; ch < 2; ch++) {
                int gr = rowBase + wm * 32 + mi * 16 + g + ch * 8;
                int gc = colBase + wn * 32 + ni * 8 + qp * 2;
                if (gc < N) {
                    if (SPLIT) {
                        long o = (long)gr * ldc + gc;
                        split1(acc[mi][ni][ch * 2],     &Ch[o],     &Cl[o]);
                        if (gc + 1 < N)
                            split1(acc[mi][ni][ch * 2 + 1], &Ch[o + 1], &Cl[o + 1]);
                    } else {
                        *(float2*)&C[(long)gr * ldc + gc] =
                            make_float2(acc[mi][ni][ch * 2], acc[mi][ni][ch * 2 + 1]);
                    }
                }
            }
}

// Merged prep GEMMs: z<8: P[h] = Wadd[h]@akT (hi/lo split store);
//                    z>=8: v2^T[h] = Wv1[h]@akT (fp32)
__global__ __launch_bounds__(256) void pv_gemm()
{
    int z = blockIdx.z;
    int h = z & 7;
    if (z < 8) {
        bf3_tile<true>(g_wah + (long)h * Cd * Cd, g_wal + (long)h * Cd * Cd, Cd,
                       g_akTh, g_akTl, PLD,
                       nullptr, g_Ph + (long)h * Cd * PLD, g_Pl + (long)h * Cd * PLD,
                       PLD, LXd, Cd);
    } else {
        bf3_tile<false>(g_wv1h + (long)h * Cd * Cd, g_wv1l + (long)h * Cd * Cd, Cd,
                        g_akTh, g_akTl, PLD,
                        g_v2t + (long)h * Cd * PLD, nullptr, nullptr, PLD, LXd, Cd);
    }
}

// attn_a logits: query @ P[h]
__global__ __launch_bounds__(256) void attn_gemm()
{
    int h = blockIdx.z;
    bf3_tile<false>(g_qh, g_ql, Cd,
                    g_Ph + (long)h * Cd * PLD, g_Pl + (long)h * Cd * PLD, PLD,
                    g_attn_a + h * LXd, nullptr, nullptr, KAA, LXd, Cd);
}

// output GEMM partial slabs (split-K, 8 slabs in one launch)
__global__ __launch_bounds__(256) void out_gemm()
{
    int z = blockIdx.z;
    const __nv_bfloat16 *Ahg, *Alg, *Bhg, *Blg;
    int lda, kOff, kLen;
    if (z < 4) {
        Ahg = g_aggh; Alg = g_aggl; Bhg = g_wv0h; Blg = g_wv0l;
        lda = Hd * Cd; kOff = z * 512; kLen = 512;
    } else {
        int zi = z - 4;
        Ahg = g_aah;  Alg = g_aal;  Bhg = g_v2fh; Blg = g_v2fl;
        lda = KAA; kOff = zi * 608; kLen = (zi == 3) ? 576 : 608;
    }
    bf3_tile<false>(Ahg + kOff, Alg + kOff, lda,
                    Bhg + (long)kOff * Cd, Blg + (long)kOff * Cd, Cd,
                    g_part[z], nullptr, nullptr, Cd, Cd, kLen);
}

// ---------------------------------------------------------------------------
// Scrambled attn_s logits via pipelined bf16x3 MMA.
// Block (r,l,h): M[j,e] = sum_c' qf[r+32j,c'] * flat[slin[c']][e]  (64x256x256)
// then logit[p,j] = Ws[h,l,p*64+j,:] . M[j,:]
// ---------------------------------------------------------------------------
constexpr int SLOG_STG  = 22016;                        // per-stage elems
constexpr int SLOG_SMEM = 2 * SLOG_STG * 2;             // 88064 (>= Ms 68608)

__global__ __launch_bounds__(256) void slog_mma(const float* __restrict__ W_attn)
{
    extern __shared__ char sm[];
    __nv_bfloat16* smb = (__nv_bfloat16*)sm;
    float* Ms = (float*)sm;                              // [64][268] overlays stages
    __shared__ int slin[256];

    const int r = blockIdx.x, l = blockIdx.y, h = blockIdx.z;
    const int tid = threadIdx.x, lane = tid & 31, warp = tid >> 5;
    const int wm = warp & 1, wn = warp >> 1;
    const int p2 = r >> 3, b = r & 7;
    slin[tid] = g_lin[((256 * b + tid) * Hd + h) * 16 + l * 4 + p2];
    __syncthreads();

    auto issue = [&](int ck, int s) {
        __nv_bfloat16* Ah = smb + s * SLOG_STG;
        __nv_bfloat16* Al = Ah + 2560;
        __nv_bfloat16* Bh = Al + 2560;
        __nv_bfloat16* Bl = Bh + 8448;
        {
            int j = tid >> 2, q = tid & 3;
            long off = (long)(r + 32 * j) * Cd + ck + q * 8;
            cp16(Ah + j * 40 + q * 8, g_qh + off);
            cp16(Al + j * 40 + q * 8, g_ql + off);
        }
#pragma unroll
        for (int i = 0; i < 4; i++) {
            int idx = tid + i * 256;
            int kr = idx >> 5, q = idx & 31;
            long off = (long)slin[ck + kr] * Cd + q * 8;
            cp16(Bh + kr * 264 + q * 8, g_fh + off);
            cp16(Bl + kr * 264 + q * 8, g_fl + off);
        }
        CP_COMMIT();
    };

    float acc[2][8][4] = {};
    issue(0, 0);
    for (int it = 0; it < 8; it++) {
        if (it + 1 < 8) { issue((it + 1) << 5, (it + 1) & 1); CP_WAIT1(); }
        else            { CP_WAIT0(); }
        __syncthreads();
        __nv_bfloat16* Ah = smb + (it & 1) * SLOG_STG;
        __nv_bfloat16* Al = Ah + 2560;
        __nv_bfloat16* Bh = Al + 2560;
        __nv_bfloat16* Bl = Bh + 8448;
#pragma unroll
        for (int kk = 0; kk < 32; kk += 16) {
            unsigned ah[2][4], al[2][4];
#pragma unroll
            for (int mi = 0; mi < 2; mi++) {
                int rr = wm * 32 + mi * 16 + (lane & 15);
                int cc = kk + (lane >> 4) * 8;
                ldsm_x4(smem_u32(&Ah[rr * 40 + cc]), ah[mi][0], ah[mi][1], ah[mi][2], ah[mi][3]);
                ldsm_x4(smem_u32(&Al[rr * 40 + cc]), al[mi][0], al[mi][1], al[mi][2], al[mi][3]);
            }
#pragma unroll
            for (int nb = 0; nb < 4; nb++) {
                unsigned bh[4], bl[4];
                int rr = kk + (lane & 15);
                int cc = wn * 64 + nb * 16 + (lane >> 4) * 8;
                ldsm_x4_trans(smem_u32(&Bh[rr * 264 + cc]), bh[0], bh[1], bh[2], bh[3]);
                ldsm_x4_trans(smem_u32(&Bl[rr * 264 + cc]), bl[0], bl[1], bl[2], bl[3]);
#pragma unroll
                for (int mi = 0; mi < 2; mi++)
#pragma unroll
                    for (int t = 0; t < 2; t++) {
                        int ni = nb * 2 + t;
                        mma_bf16(acc[mi][ni], ah[mi], bh[t * 2], bh[t * 2 + 1]);
                        mma_bf16(acc[mi][ni], ah[mi], bl[t * 2], bl[t * 2 + 1]);
                        mma_bf16(acc[mi][ni], al[mi], bh[t * 2], bh[t * 2 + 1]);
                    }
            }
        }
        __syncthreads();
    }

    // acc -> Ms (overlays stage buffers; safe after the loop's trailing barrier)
    const int g = lane >> 2, qp = lane & 3;
#pragma unroll
    for (int mi = 0; mi < 2; mi++)
#pragma unroll
        for (int ni = 0; ni < 8; ni++)
#pragma unroll
            for (int ch = 0; ch < 2; ch++) {
                int row = wm * 32 + mi * 16 + g + ch * 8;
                int col = wn * 64 + ni * 8 + qp * 2;
                *(float2*)&Ms[row * 268 + col] =
                    make_float2(acc[mi][ni][ch * 2], acc[mi][ni][ch * 2 + 1]);
            }
    __syncthreads();

    // stage 2: one logit per thread
    int p = tid >> 6, j = tid & 63;
    int cstar = p * 64 + j;
    const float4* w4 = (const float4*)(W_attn + ((long)(h * Ld + l) * Cd + cstar) * Cd);
    const float* mrow = Ms + j * 268;
    float s = 0.f;
#pragma unroll 4
    for (int e4 = 0; e4 < 64; e4++) {
        float4 w = w4[e4];
        s += w.x * mrow[e4 * 4] + w.y * mrow[e4 * 4 + 1]
           + w.z * mrow[e4 * 4 + 2] + w.w * mrow[e4 * 4 + 3];
    }
    int q = r + 32 * j;
    g_slog[(q * Hd + h) * 16 + l * 4 + p] = s;
}

// ---------------------------------------------------------------------------
// fp32 off-projection (index-sensitive, stays fp32): split-K, 4 slabs.
// ---------------------------------------------------------------------------
__global__ void off_gemm(const float* __restrict__ A, const float* __restrict__ B)
{
    __shared__ float As[16][68];
    __shared__ float Bs[16][68];
    const int tid = threadIdx.x;
    const int kOff = blockIdx.z * 64;
    float* Cm = g_offp[blockIdx.z];
    const int rowBase = blockIdx.y * 64, colBase = blockIdx.x * 64;
    const int tr = (tid >> 4) * 4, tc = (tid & 15) * 4;
    float acc[4][4] = {};

    for (int kt = 0; kt < 64; kt += 16) {
#pragma unroll
        for (int i = 0; i < 4; i++) {
            int idx = tid + i * 256;
            int ar = idx >> 4, ac = idx & 15;
            As[ac][ar] = A[(long)(rowBase + ar) * Cd + kOff + kt + ac];
        }
#pragma unroll
        for (int i = 0; i < 4; i++) {
            int idx = tid + i * 256;
            int bn = idx >> 4, bk = idx & 15;
            Bs[bk][bn] = B[(long)(colBase + bn) * Cd + kOff + kt + bk];
        }
        __syncthreads();
#pragma unroll
        for (int k = 0; k < 16; k++) {
            float4 av = *(const float4*)&As[k][tr];
            float4 bv = *(const float4*)&Bs[k][tc];
            float a[4] = {av.x, av.y, av.z, av.w};
            float b[4] = {bv.x, bv.y, bv.z, bv.w};
#pragma unroll
            for (int i = 0; i < 4; i++)
#pragma unroll
                for (int j = 0; j < 4; j++) acc[i][j] += a[i] * b[j];
        }
        __syncthreads();
    }
#pragma unroll
    for (int i = 0; i < 4; i++)
#pragma unroll
        for (int j = 0; j < 4; j++)
            Cm[(long)(rowBase + tr + i) * Cd + colBase + tc + j] = acc[i][j];
}

// ---------------------------------------------------------------------------
// Merged conversion: query, flat, Wadd, Wv1 -> bf16 hi/lo
// ---------------------------------------------------------------------------
constexpr long CVT_NQ = (long)LQd * Cd;            // 524288
constexpr long CVT_NF = (long)LEN * Cd;            // 1392640
constexpr long CVT_NW = (long)Hd * Cd * Cd;        // 524288
constexpr long CVT_TOT = CVT_NQ + CVT_NF + 2 * CVT_NW;   // 2965504

__global__ void cvt_all(const float* __restrict__ query, const float* __restrict__ flat,
                        const float* __restrict__ W_attn, const float* __restrict__ W_v)
{
    long i = (long)blockIdx.x * 256 + threadIdx.x;
    if (i < CVT_NQ) {
        split1(query[i], &g_qh[i], &g_ql[i]);
    } else if (i < CVT_NQ + CVT_NF) {
        long j = i - CVT_NQ;
        split1(flat[j], &g_fh[j], &g_fl[j]);
    } else if (i < CVT_NQ + CVT_NF + CVT_NW) {
        long j = i - (CVT_NQ + CVT_NF);
        int h = (int)(j >> 16);
        long rem = j & 65535;
        split1(W_attn[((long)(4 * h + 4) << 16) + rem], &g_wah[j], &g_wal[j]);
    } else {
        long j = i - (CVT_NQ + CVT_NF + CVT_NW);
        int h = (int)(j >> 16);
        long rem = j & 65535;
        split1(W_v[((long)(2 * h + 1) << 16) + rem], &g_wv1h[j], &g_wv1l[j]);
    }
}

// ak [300][256] -> akT hi/lo [256][304] (zero-padded cols 300..303)
__global__ void cvt_akT(const float* __restrict__ ak)
{
    __shared__ float t[32][33];
    int k0 = blockIdx.x * 32;
    int x0 = blockIdx.y * 32;
    int x = threadIdx.x, y = threadIdx.y;
    for (int i = 0; i < 32; i += 8) {
        int xx = x0 + y + i;
        t[y + i][x] = (xx < LXd) ? ak[(long)xx * Cd + k0 + x] : 0.f;
    }
    __syncthreads();
    for (int i = 0; i < 32; i += 8) {
        int kk = k0 + y + i;
        int xx = x0 + x;
        if (xx < PLD) {
            long o = (long)kk * PLD + xx;
            split1(t[x][y + i], &g_akTh[o], &g_akTl[o]);
        }
    }
}

__global__ void prep_headw(const float* __restrict__ W_mix, const float* __restrict__ b_v)
{
    int c = threadIdx.x;
    float m = -1e30f;
    for (int j = 0; j <= Hd; j++) m = fmaxf(m, W_mix[c * (Hd + 1) + j]);
    float e[Hd + 1];
    float Z = 0.f;
    for (int j = 0; j <= Hd; j++) { e[j] = expf(W_mix[c * (Hd + 1) + j] - m); Z += e[j]; }
    float invZ = 1.f / Z;
    for (int j = 0; j <= Hd; j++) g_headw[j * Cd + c] = e[j] * invZ;
    for (int h = 0; h < Hd; h++)  g_bv0f[h * Cd + c] = e[h] * invZ * b_v[(2 * h) * Cd + c];
}

// wv0ft[h][e][c] = head_w[h][c] * W_v[2h][c][e]  -> bf16 hi/lo
__global__ void prep_fold(const float* __restrict__ W_v)
{
    __shared__ float t[32][33];
    int h = blockIdx.z;
    int e0 = blockIdx.x * 32, c0 = blockIdx.y * 32;
    int x = threadIdx.x, y = threadIdx.y;
    for (int i = 0; i < 32; i += 8) {
        int cc = c0 + y + i;
        t[y + i][x] = W_v[((long)(2 * h) * Cd + cc) * Cd + e0 + x];
    }
    __syncthreads();
    for (int i = 0; i < 32; i += 8) {
        int ee = e0 + y + i;
        int cc = c0 + x;
        float v = g_headw[h * Cd + cc] * t[x][y + i];
        long o = ((long)h * Cd + ee) * Cd + cc;
        split1(v, &g_wv0h[o], &g_wv0l[o]);
    }
}

// v2f[h*300+x][c] = head_w[h][c]*(v2t[h][c][x] + bv1[h][c]) -> bf16 hi/lo
__global__ void fold_v2t(const float* __restrict__ b_v)
{
    __shared__ float t[32][33];
    int h = blockIdx.z;
    int c0 = blockIdx.x * 32, x0 = blockIdx.y * 32;
    int x = threadIdx.x, y = threadIdx.y;
    for (int i = 0; i < 32; i += 8) {
        int cc = c0 + y + i;
        t[y + i][x] = g_v2t[((long)h * Cd + cc) * PLD + x0 + x];
    }
    __syncthreads();
    for (int i = 0; i < 32; i += 8) {
        int xx = x0 + y + i;
        int cc = c0 + x;
        if (xx < LXd) {
            float v = g_headw[h * Cd + cc] * (t[x][y + i] + b_v[(2 * h + 1) * Cd + cc]);
            long o = (long)(h * LXd + xx) * Cd + cc;
            split1(v, &g_v2fh[o], &g_v2fl[o]);
        }
    }
}

__global__ void loc_kernel(const float* __restrict__ ref, const float* __restrict__ b_off,
                           const int* __restrict__ iss, const int* __restrict__ lsi)
{
    int id = blockIdx.x * 256 + threadIdx.x;
    if (id >= LQd * Hd * Ld * Pd) return;
    int q = id >> 7;
    int r = id & 127;
    int hh = r >> 4;
    int l = (r >> 2) & 3;
    int p = r & 3;
    int j = ((hh * Ld + l) * Pd + p) * 2;
    float off0 = g_offp[0][q * Cd + j]     + g_offp[1][q * Cd + j]
               + g_offp[2][q * Cd + j]     + g_offp[3][q * Cd + j]     + b_off[j];
    float off1 = g_offp[0][q * Cd + j + 1] + g_offp[1][q * Cd + j + 1]
               + g_offp[2][q * Cd + j + 1] + g_offp[3][q * Cd + j + 1] + b_off[j + 1];
    int W0 = iss[l * 2], W1 = iss[l * 2 + 1];
    float ref0 = ref[(q * Ld + l) * 2];
    float ref1 = ref[(q * Ld + l) * 2 + 1];
    float loc0 = ref0 + off0 / (float)W1;
    float loc1 = ref1 + off1 / (float)W0;
    loc0 = fminf(fmaxf(loc0, 0.f), 0.999f);
    loc1 = fminf(fmaxf(loc1, 0.f), 0.999f);
    int ix = (int)(loc0 * (float)W0);
    int iy = (int)(loc1 * (float)W1);
    g_lin[id] = ix + iy * W0 + lsi[l];
}

// ---------------------------------------------------------------------------
// Merged softmax + aggregation: one block per q, one warp per head.
// ---------------------------------------------------------------------------
__global__ __launch_bounds__(256) void fuse_kernel(const float* __restrict__ flat)
{
    __shared__ float sws[Hd][16];
    __shared__ int   slinS[Hd][16];

    const int q = blockIdx.x;
    const int w = threadIdx.x >> 5, lane = threadIdx.x & 31;
    const int h = w;
    const int base16 = (q * Hd + h) * 16;

    float lg16 = -1e30f;
    if (lane < 16) {
        slinS[w][lane] = g_lin[base16 + lane];
        lg16 = g_slog[base16 + lane];
    }
    const long arow = (long)q * KAA + h * LXd;
    float la[10];
#pragma unroll
    for (int j = 0; j < 9; j++) la[j] = g_attn_a[arow + lane + 32 * j];
    la[9] = (lane < 12) ? g_attn_a[arow + 288 + lane] : -1e30f;

    float m = lg16;
#pragma unroll
    for (int j = 0; j < 10; j++) m = fmaxf(m, la[j]);
#pragma unroll
    for (int o = 16; o > 0; o >>= 1) m = fmaxf(m, __shfl_xor_sync(0xffffffffu, m, o));

    float e[10];
    float csum = 0.f;
#pragma unroll
    for (int j = 0; j < 10; j++) { e[j] = expf(la[j] - m); csum += e[j]; }
    float es = (lane < 16) ? expf(lg16 - m) : 0.f;
    csum += es;
#pragma unroll
    for (int o = 16; o > 0; o >>= 1) csum += __shfl_xor_sync(0xffffffffu, csum, o);
    const float invZ = 1.f / csum;

#pragma unroll
    for (int j = 0; j < 9; j++) {
        long o2 = arow + lane + 32 * j;
        split1(e[j] * invZ, &g_aah[o2], &g_aal[o2]);
    }
    if (lane < 12) {
        long o2 = arow + 288 + lane;
        split1(e[9] * invZ, &g_aah[o2], &g_aal[o2]);
    }

    float wk = es * invZ;
    if (lane < 16) sws[w][lane] = wk;
    float ss = wk;
#pragma unroll
    for (int o = 16; o > 0; o >>= 1) ss += __shfl_xor_sync(0xffffffffu, ss, o);
    if (lane == 0) g_ssum[q * Hd + h] = ss;
    __syncwarp();

    float agg[8] = {};
#pragma unroll
    for (int k = 0; k < 16; k++) {
        const float* row = flat + (long)slinS[w][k] * Cd + lane;
        float wv = sws[w][k];
#pragma unroll
        for (int j = 0; j < 8; j++) agg[j] += wv * row[32 * j];
    }
    const long ob = (long)(q * Hd + h) * Cd + lane;
#pragma unroll
    for (int j = 0; j < 8; j++) split1(agg[j], &g_aggh[ob + 32 * j], &g_aggl[ob + 32 * j]);
}

// out = q*headw_last + sum_h ssum*bv0f + 8 split-K partials
__global__ void combine_out(const float* __restrict__ query, float* __restrict__ out)
{
    int i = blockIdx.x * 256 + threadIdx.x;
    int c = i & 255, q = i >> 8;
    float v = query[i] * g_headw[Hd * Cd + c];
#pragma unroll
    for (int h = 0; h < Hd; h++) v += g_ssum[q * Hd + h] * g_bv0f[h * Cd + c];
#pragma unroll
    for (int z = 0; z < 8; z++) v += g_part[z][i];
    out[i] = v;
}

// ---------------------------------------------------------------------------
extern "C" void kernel_launch(void* const* d_in, const int* in_sizes, int n_in,
                              void* d_out, int out_size)
{
    const float* query  = (const float*)d_in[0];
    const float* ref    = (const float*)d_in[1];
    const float* flat   = (const float*)d_in[2];
    const int*   iss    = (const int*)  d_in[3];
    const float* ak     = (const float*)d_in[4];
    const int*   lsi    = (const int*)  d_in[5];
    const float* W_off  = (const float*)d_in[6];
    const float* b_off  = (const float*)d_in[7];
    const float* W_attn = (const float*)d_in[8];
    const float* W_v    = (const float*)d_in[9];
    const float* b_v    = (const float*)d_in[10];
    const float* W_mix  = (const float*)d_in[11];
    float* out = (float*)d_out;

    static int smem_set = 0;
    if (!smem_set) {
        cudaFuncSetAttribute(slog_mma,
                             cudaFuncAttributeMaxDynamicSharedMemorySize, SLOG_SMEM);
        cudaFuncSetAttribute(pv_gemm,
                             cudaFuncAttributeMaxDynamicSharedMemorySize, BF3_SMEM);
        cudaFuncSetAttribute(attn_gemm,
                             cudaFuncAttributeMaxDynamicSharedMemorySize, BF3_SMEM);
        cudaFuncSetAttribute(out_gemm,
                             cudaFuncAttributeMaxDynamicSharedMemorySize, BF3_SMEM);
        smem_set = 1;
    }

    // operand conversions (merged)
    cvt_all<<<(int)(CVT_TOT / 256), 256>>>(query, flat, W_attn, W_v);
    cvt_akT<<<dim3(Cd / 32, 10), dim3(32, 8)>>>(ak);

    // off = query @ W_off^T (fp32, split-K 4 slabs) ; sampling indices
    off_gemm<<<dim3(4, 32, 4), 256>>>(query, W_off);
    loc_kernel<<<(LQd * Hd * Ld * Pd + 255) / 256, 256>>>(ref, b_off, iss, lsi);

    // P[h] + v2t[h] prep GEMMs in ONE launch, then attn_a logits
    pv_gemm<<<dim3((LXd + 63) / 64, Cd / 128, 16), 256, BF3_SMEM>>>();
    attn_gemm<<<dim3((LXd + 63) / 64, LQd / 128, Hd), 256, BF3_SMEM>>>();

    // scrambled attn_s logits (pipelined bf16x3 MMA)
    slog_mma<<<dim3(32, Ld, Hd), 256, SLOG_SMEM>>>(W_attn);

    // head mixing + value-side folds
    prep_headw<<<1, 256>>>(W_mix, b_v);
    fold_v2t<<<dim3(Cd / 32, 10, Hd), dim3(32, 8)>>>(b_v);
    prep_fold<<<dim3(8, 8, Hd), dim3(32, 8)>>>(W_v);

    // softmax + aggregation (merged: block per q, warp per head)
    fuse_kernel<<<LQd, 256>>>(flat);

    // output GEMMs: 8 split-K slabs in ONE launch
    out_gemm<<<dim3(Cd / 64, LQd / 128, 8), 256, BF3_SMEM>>>();

    combine_out<<<LQd * Cd / 256, 256>>>(query, out);
}